// round 8
// baseline (speedup 1.0000x reference)
#include <cuda_runtime.h>
#include <cuda_fp16.h>
#include <cstdint>

// ---------------------------------------------------------------------------
// TransformerEncoderLayer  S=1024 B=4 D=1024 H=16 HD=64 DFF=4096, LSQ 4-bit
// Round 8: hgemm -> 8 warps (2x4), warp tile 64x32, 256 thr, ~110 regs
// => 2 CTAs/SM with 16 warps/SM (was 11% occ, tensor 34%). Everything else
// unchanged from round 7 for attribution.
// ---------------------------------------------------------------------------

#define S_DIM   1024
#define B_DIM   4
#define D_DIM   1024
#define H_DIM   16
#define HD_DIM  64
#define DFF_DIM 4096
#define MROWS   (S_DIM * B_DIM)        // 4096 token rows
#define NBH     (B_DIM * H_DIM)        // 64 batch*head

// ---------------- scratch (no cudaMalloc allowed) ----------------
__device__ __align__(16) __half g_win_q [3 * D_DIM * D_DIM];
__device__ __align__(16) __half g_wout_q[D_DIM * D_DIM];
__device__ __align__(16) __half g_w1_q  [DFF_DIM * D_DIM];
__device__ __align__(16) __half g_w2_q  [(size_t)D_DIM * DFF_DIM];
__device__ __align__(16) __half g_src2h [MROWS * D_DIM];
__device__ __align__(16) __half g_qkh   [MROWS * D_DIM];
__device__ __align__(16) __half g_qk2   [(size_t)MROWS * 2048];  // q|k fused
__device__ __align__(16) __half g_vh    [MROWS * D_DIM];
__device__ __align__(16) __half g_ctxh  [MROWS * D_DIM];
__device__ __align__(16) float  g_res   [MROWS * D_DIM];
__device__ __align__(16) __half g_src2bh[MROWS * D_DIM];
__device__ __align__(16) __half g_hbufh [(size_t)MROWS * DFF_DIM];

// ---------------- PTX helpers ----------------
__device__ __forceinline__ uint32_t smem_u32(const void* p) {
    return (uint32_t)__cvta_generic_to_shared(p);
}
__device__ __forceinline__ void cp16(void* smem, const void* g) {
    asm volatile("cp.async.cg.shared.global [%0], [%1], 16;"
                 :: "r"(smem_u32(smem)), "l"(g));
}
__device__ __forceinline__ void cp_commit() {
    asm volatile("cp.async.commit_group;");
}
template <int N>
__device__ __forceinline__ void cp_wait() {
    asm volatile("cp.async.wait_group %0;" :: "n"(N));
}
__device__ __forceinline__ void ldsm4(unsigned* r, const void* p) {
    unsigned a = smem_u32(p);
    asm volatile("ldmatrix.sync.aligned.m8n8.x4.shared.b16 {%0,%1,%2,%3}, [%4];"
                 : "=r"(r[0]), "=r"(r[1]), "=r"(r[2]), "=r"(r[3]) : "r"(a));
}
__device__ __forceinline__ void ldsm4t(unsigned* r, const void* p) {
    unsigned a = smem_u32(p);
    asm volatile("ldmatrix.sync.aligned.m8n8.x4.trans.shared.b16 {%0,%1,%2,%3}, [%4];"
                 : "=r"(r[0]), "=r"(r[1]), "=r"(r[2]), "=r"(r[3]) : "r"(a));
}
__device__ __forceinline__ void mma16816(float* d, const unsigned* a,
                                         unsigned b0, unsigned b1) {
    asm volatile(
        "mma.sync.aligned.m16n8k16.row.col.f32.f16.f16.f32 "
        "{%0,%1,%2,%3}, {%4,%5,%6,%7}, {%8,%9}, {%0,%1,%2,%3};\n"
        : "+f"(d[0]), "+f"(d[1]), "+f"(d[2]), "+f"(d[3])
        : "r"(a[0]), "r"(a[1]), "r"(a[2]), "r"(a[3]), "r"(b0), "r"(b1));
}
__device__ __forceinline__ unsigned packh2(float x, float y) {
    __half2 h = __floats2half2_rn(x, y);
    return *reinterpret_cast<unsigned*>(&h);
}

// ---------------- fused LSQ quant (all 4 weight mats, 1 launch) -------------
__global__ void __launch_bounds__(256)
quant4_kernel(const float4* __restrict__ w0, const float4* __restrict__ w1,
              const float4* __restrict__ w2, const float4* __restrict__ w3,
              const float* __restrict__ a0, const float* __restrict__ a1,
              const float* __restrict__ a2, const float* __restrict__ a3,
              uint2* __restrict__ o0, uint2* __restrict__ o1,
              uint2* __restrict__ o2, uint2* __restrict__ o3) {
    int j = blockIdx.x * blockDim.x + threadIdx.x;
    const float4* w; const float* a; uint2* o;
    if (j < 786432)                     { w = w0; a = a0; o = o0; }
    else if ((j -= 786432) < 262144)    { w = w1; a = a1; o = o1; }
    else if ((j -= 262144) < 1048576)   { w = w2; a = a2; o = o2; }
    else { j -= 1048576;                  w = w3; a = a3; o = o3; }
    const float ia = 1.0f / __ldg(a);
    const float4 v = w[j];
    const float q0 = rintf(fminf(fmaxf(v.x * ia, -8.0f), 7.0f));
    const float q1 = rintf(fminf(fmaxf(v.y * ia, -8.0f), 7.0f));
    const float q2 = rintf(fminf(fmaxf(v.z * ia, -8.0f), 7.0f));
    const float q3 = rintf(fminf(fmaxf(v.w * ia, -8.0f), 7.0f));
    o[j] = make_uint2(packh2(q0, q1), packh2(q2, q3));
}

// ---------------- LayerNorm (fp32 math, fp16 outputs, float4 I/O) -----------
template <bool WRITE_QK>
__global__ void __launch_bounds__(256)
ln_kernel(const float* __restrict__ x, const float* __restrict__ gam,
          const float* __restrict__ bet, const float* __restrict__ pos,
          __half* __restrict__ out, __half* __restrict__ qk) {
    __shared__ float red[256];
    const int row = blockIdx.x;
    const int t = threadIdx.x;
    const size_t rb = (size_t)row * D_DIM;

    const float4 xv = *reinterpret_cast<const float4*>(x + rb + 4 * t);
    float s = xv.x + xv.y + xv.z + xv.w;
    red[t] = s; __syncthreads();
    for (int off = 128; off > 0; off >>= 1) {
        if (t < off) red[t] += red[t + off];
        __syncthreads();
    }
    const float mean = red[0] * (1.0f / D_DIM);
    __syncthreads();

    const float d0 = xv.x - mean, d1 = xv.y - mean,
                d2 = xv.z - mean, d3 = xv.w - mean;
    red[t] = d0 * d0 + d1 * d1 + d2 * d2 + d3 * d3;
    __syncthreads();
    for (int off = 128; off > 0; off >>= 1) {
        if (t < off) red[t] += red[t + off];
        __syncthreads();
    }
    const float rstd = rsqrtf(red[0] * (1.0f / D_DIM) + 1e-5f);

    const float4 gv = *reinterpret_cast<const float4*>(gam + 4 * t);
    const float4 bv = *reinterpret_cast<const float4*>(bet + 4 * t);
    const float y0 = d0 * rstd * gv.x + bv.x;
    const float y1 = d1 * rstd * gv.y + bv.y;
    const float y2 = d2 * rstd * gv.z + bv.z;
    const float y3 = d3 * rstd * gv.w + bv.w;
    *reinterpret_cast<uint2*>(out + rb + 4 * t) =
        make_uint2(packh2(y0, y1), packh2(y2, y3));
    if (WRITE_QK) {
        const float4 pv = *reinterpret_cast<const float4*>(pos + rb + 4 * t);
        *reinterpret_cast<uint2*>(qk + rb + 4 * t) =
            make_uint2(packh2(y0 + pv.x, y1 + pv.y),
                       packh2(y2 + pv.z, y3 + pv.w));
    }
}

// ---------------- pipelined fp16 NT GEMM (8 warps, warp tile 64x32) ---------
// C[m,n] = s(col)*alpha * sum_k A[m,k]*B[n,k]  (+bias, +resid fp32, relu)
// BM=BN=128, BK=32, 256 threads = 8 warps (2 M x 4 N), 2-stage cp.async.
__global__ void __launch_bounds__(256)
hgemm(const __half* __restrict__ A, const __half* __restrict__ Bm,
      float* __restrict__ C32, __half* __restrict__ C16,
      const float* __restrict__ bias, const float* __restrict__ resid,
      const float* __restrict__ alphaPtr,
      int K, int lda, int ldb, int ldc,
      float scaleLo, float scaleHi, int splitCol, int relu) {
    __shared__ alignas(16) __half As[2][128][40];
    __shared__ alignas(16) __half Bs[2][128][40];

    const int bm = blockIdx.y * 128;
    const int bn = blockIdx.x * 128;
    const int tid = threadIdx.x;
    const int wid = tid >> 5;
    const int lane = tid & 31;
    const int wm = (wid & 1) * 64;          // 2 warps over M
    const int wn = (wid >> 1) * 32;         // 4 warps over N
    const int g = lane >> 2, tg = lane & 3;
    const int lrow = lane & 15;
    const int lcol = (lane >> 4) * 8;

    float acc[4][4][4];
#pragma unroll
    for (int i = 0; i < 4; i++)
#pragma unroll
        for (int j = 0; j < 4; j++)
#pragma unroll
            for (int e = 0; e < 4; e++) acc[i][j][e] = 0.f;

    const int TILES = K >> 5;

    // loader: 2 A + 2 B cp16 per thread per stage (128 rows x 4 int4 each)
#define LOAD_TILE(kt, st)                                                     \
    {                                                                         \
        const int k0 = (kt) << 5;                                             \
        _Pragma("unroll")                                                     \
        for (int t = 0; t < 2; t++) {                                         \
            const int i = tid + t * 256;                                      \
            const int r = i >> 2, c = (i & 3) * 8;                            \
            cp16(&As[st][r][c], A + (long)(bm + r) * lda + k0 + c);           \
            cp16(&Bs[st][r][c], Bm + (long)(bn + r) * ldb + k0 + c);          \
        }                                                                     \
    }

    LOAD_TILE(0, 0);
    cp_commit();

    for (int kt = 0; kt < TILES; ++kt) {
        if (kt + 1 < TILES) LOAD_TILE(kt + 1, (kt + 1) & 1);
        cp_commit();
        cp_wait<1>();
        __syncthreads();

        const int st = kt & 1;
#pragma unroll
        for (int ks = 0; ks < 32; ks += 16) {
            unsigned a[4][4];
#pragma unroll
            for (int mt = 0; mt < 4; mt++)
                ldsm4(a[mt], &As[st][wm + mt * 16 + lrow][ks + lcol]);
            unsigned b[4][2];
#pragma unroll
            for (int i = 0; i < 2; i++) {
                unsigned b4[4];
                ldsm4(b4, &Bs[st][wn + i * 16 + lrow][ks + lcol]);
                b[2 * i][0] = b4[0]; b[2 * i][1] = b4[2];
                b[2 * i + 1][0] = b4[1]; b[2 * i + 1][1] = b4[3];
            }
#pragma unroll
            for (int mt = 0; mt < 4; mt++)
#pragma unroll
                for (int nt = 0; nt < 4; nt++)
                    mma16816(acc[mt][nt], a[mt], b[nt][0], b[nt][1]);
        }
        __syncthreads();
    }
#undef LOAD_TILE

    const float al = alphaPtr ? __ldg(alphaPtr) : 1.0f;
#pragma unroll
    for (int mt = 0; mt < 4; mt++) {
#pragma unroll
        for (int nt = 0; nt < 4; nt++) {
            const int row0 = bm + wm + mt * 16 + g;
            const int col0 = bn + wn + nt * 8 + tg * 2;
            const float sc = (col0 < splitCol ? scaleLo : scaleHi) * al;
            float bx = 0.f, by = 0.f;
            if (bias) {
                const float2 bb = *reinterpret_cast<const float2*>(&bias[col0]);
                bx = bb.x; by = bb.y;
            }
#pragma unroll
            for (int h = 0; h < 2; ++h) {
                const int row = row0 + h * 8;
                float v0 = acc[mt][nt][2 * h] * sc + bx;
                float v1 = acc[mt][nt][2 * h + 1] * sc + by;
                if (resid) {
                    const float2 rr = *reinterpret_cast<const float2*>(
                        &resid[(long)row * ldc + col0]);
                    v0 += rr.x; v1 += rr.y;
                }
                if (relu) { v0 = fmaxf(v0, 0.f); v1 = fmaxf(v1, 0.f); }
                if (C32)
                    *reinterpret_cast<float2*>(&C32[(long)row * ldc + col0]) =
                        make_float2(v0, v1);
                if (C16)
                    *reinterpret_cast<__half2*>(&C16[(long)row * ldc + col0]) =
                        __floats2half2_rn(v0, v1);
            }
        }
    }
}

// ---------------- fused flash attention (mma.sync) ----------------
// grid (8, 64): blockIdx.x = q-tile (128 rows), blockIdx.y = z = b*16+h.
// 256 threads = 8 warps; warp handles 16 q rows. Q pre-scaled by 1/8.
// Q/K in qk2: elem (s,b,h,d) = s*8192 + b*2048 + h*64 + d (K at +1024).
// V/O: s*4096 + b*1024 + h*64 + d.
#define FL_SMEM (3 * 128 * 72 * 2)
__global__ void __launch_bounds__(256)
flash_kernel(const __half* __restrict__ QK2, const __half* __restrict__ Vg,
             __half* __restrict__ O) {
    extern __shared__ __half fsm[];
    __half (*Qs)[72] = reinterpret_cast<__half(*)[72]>(fsm);
    __half (*Ks)[72] = reinterpret_cast<__half(*)[72]>(fsm + 128 * 72);
    __half (*Vs)[72] = reinterpret_cast<__half(*)[72]>(fsm + 2 * 128 * 72);

    const int z = blockIdx.y;
    const int qt = blockIdx.x;
    const int tid = threadIdx.x;
    const int wid = tid >> 5, lane = tid & 31;
    const int g = lane >> 2, tg = lane & 3;
    const int lrow = lane & 15, lcol = (lane >> 4) * 8;
    const long qOff = (long)(z >> 4) * 2048 + (z & 15) * 64;
    const long vOff = (long)z * 64;
    const int wq = wid * 16;

    for (int i = tid; i < 128 * 8; i += 256) {
        const int r = i >> 3, c = (i & 7) * 8;
        *reinterpret_cast<int4*>(&Qs[r][c]) =
            *reinterpret_cast<const int4*>(QK2 + qOff + (long)(qt * 128 + r) * 8192 + c);
    }

    float accO[8][4];
#pragma unroll
    for (int i = 0; i < 8; i++)
#pragma unroll
        for (int e = 0; e < 4; e++) accO[i][e] = 0.f;
    float mrow[2] = {-1e30f, -1e30f};
    float lrow_[2] = {0.f, 0.f};

    for (int t = 0; t < 8; ++t) {
        __syncthreads();
        for (int i = tid; i < 128 * 8; i += 256) {
            const int r = i >> 3, c = (i & 7) * 8;
            *reinterpret_cast<int4*>(&Ks[r][c]) =
                *reinterpret_cast<const int4*>(QK2 + 1024 + qOff +
                                               (long)(t * 128 + r) * 8192 + c);
            *reinterpret_cast<int4*>(&Vs[r][c]) =
                *reinterpret_cast<const int4*>(Vg + vOff +
                                               (long)(t * 128 + r) * 4096 + c);
        }
        __syncthreads();

        float accS[16][4];
#pragma unroll
        for (int i = 0; i < 16; i++)
#pragma unroll
            for (int e = 0; e < 4; e++) accS[i][e] = 0.f;

#pragma unroll
        for (int kc = 0; kc < 4; ++kc) {
            unsigned a[4];
            ldsm4(a, &Qs[wq + lrow][kc * 16 + lcol]);
#pragma unroll
            for (int i = 0; i < 8; ++i) {
                unsigned b4[4];
                ldsm4(b4, &Ks[i * 16 + lrow][kc * 16 + lcol]);
                mma16816(accS[2 * i], a, b4[0], b4[2]);
                mma16816(accS[2 * i + 1], a, b4[1], b4[3]);
            }
        }

#pragma unroll
        for (int e = 0; e < 2; ++e) {
            float rmax = -1e30f;
#pragma unroll
            for (int nt = 0; nt < 16; nt++)
                rmax = fmaxf(rmax, fmaxf(accS[nt][2 * e], accS[nt][2 * e + 1]));
            rmax = fmaxf(rmax, __shfl_xor_sync(0xffffffffu, rmax, 1));
            rmax = fmaxf(rmax, __shfl_xor_sync(0xffffffffu, rmax, 2));
            const float mnew = fmaxf(mrow[e], rmax);
            const float corr = __expf(mrow[e] - mnew);
            mrow[e] = mnew;
            lrow_[e] *= corr;
#pragma unroll
            for (int nt = 0; nt < 8; nt++) {
                accO[nt][2 * e] *= corr;
                accO[nt][2 * e + 1] *= corr;
            }
            float sum = 0.f;
#pragma unroll
            for (int nt = 0; nt < 16; nt++) {
                const float p0 = __expf(accS[nt][2 * e] - mnew);
                const float p1 = __expf(accS[nt][2 * e + 1] - mnew);
                accS[nt][2 * e] = p0; accS[nt][2 * e + 1] = p1;
                sum += p0 + p1;
            }
            lrow_[e] += sum;
        }

#pragma unroll
        for (int j = 0; j < 8; ++j) {
            unsigned aP[4];
            aP[0] = packh2(accS[2 * j][0], accS[2 * j][1]);
            aP[1] = packh2(accS[2 * j][2], accS[2 * j][3]);
            aP[2] = packh2(accS[2 * j + 1][0], accS[2 * j + 1][1]);
            aP[3] = packh2(accS[2 * j + 1][2], accS[2 * j + 1][3]);
#pragma unroll
            for (int i = 0; i < 4; ++i) {
                unsigned b4[4];
                ldsm4t(b4, &Vs[j * 16 + (lane & 7) + ((lane >> 3) & 1) * 8]
                           [i * 16 + (lane >> 4) * 8]);
                mma16816(accO[2 * i], aP, b4[0], b4[1]);
                mma16816(accO[2 * i + 1], aP, b4[2], b4[3]);
            }
        }
    }

#pragma unroll
    for (int e = 0; e < 2; ++e) {
        float l = lrow_[e];
        l += __shfl_xor_sync(0xffffffffu, l, 1);
        l += __shfl_xor_sync(0xffffffffu, l, 2);
        const float inv = 1.0f / l;
        const int r = qt * 128 + wq + g + 8 * e;
#pragma unroll
        for (int nt = 0; nt < 8; nt++) {
            __half2 h = __floats2half2_rn(accO[nt][2 * e] * inv,
                                          accO[nt][2 * e + 1] * inv);
            *reinterpret_cast<__half2*>(O + (long)r * 4096 + vOff + nt * 8 + tg * 2) = h;
        }
    }
}

// ---------------------------------------------------------------------------
extern "C" void kernel_launch(void* const* d_in, const int* in_sizes, int n_in,
                              void* d_out, int out_size) {
    const float* src        = (const float*)d_in[0];
    const float* pos        = (const float*)d_in[1];
    const float* in_proj_w  = (const float*)d_in[2];
    const float* alpha_in   = (const float*)d_in[3];
    const float* out_proj_w = (const float*)d_in[4];
    const float* alpha_out  = (const float*)d_in[5];
    const float* w1         = (const float*)d_in[6];
    const float* b1         = (const float*)d_in[7];
    const float* alpha1     = (const float*)d_in[8];
    const float* w2         = (const float*)d_in[9];
    const float* b2         = (const float*)d_in[10];
    const float* alpha2     = (const float*)d_in[11];
    const float* ln1_g      = (const float*)d_in[12];
    const float* ln1_b      = (const float*)d_in[13];
    const float* ln2_g      = (const float*)d_in[14];
    const float* ln2_b      = (const float*)d_in[15];
    float* out = (float*)d_out;

    __half *win_q, *wout_q, *w1_q, *w2_q, *src2h, *qkh, *qk2, *vh;
    __half *ctxh, *src2bh, *hbufh;
    float *res;
    cudaGetSymbolAddress((void**)&win_q,  g_win_q);
    cudaGetSymbolAddress((void**)&wout_q, g_wout_q);
    cudaGetSymbolAddress((void**)&w1_q,   g_w1_q);
    cudaGetSymbolAddress((void**)&w2_q,   g_w2_q);
    cudaGetSymbolAddress((void**)&src2h,  g_src2h);
    cudaGetSymbolAddress((void**)&qkh,    g_qkh);
    cudaGetSymbolAddress((void**)&qk2,    g_qk2);
    cudaGetSymbolAddress((void**)&vh,     g_vh);
    cudaGetSymbolAddress((void**)&ctxh,   g_ctxh);
    cudaGetSymbolAddress((void**)&res,    g_res);
    cudaGetSymbolAddress((void**)&src2bh, g_src2bh);
    cudaGetSymbolAddress((void**)&hbufh,  g_hbufh);

    cudaFuncSetAttribute(flash_kernel,
                         cudaFuncAttributeMaxDynamicSharedMemorySize, FL_SMEM);

    // 1) quantize all weights (single launch)
    quant4_kernel<<<12288, 256>>>(
        (const float4*)in_proj_w, (const float4*)out_proj_w,
        (const float4*)w1, (const float4*)w2,
        alpha_in, alpha_out, alpha1, alpha2,
        (uint2*)win_q, (uint2*)wout_q, (uint2*)w1_q, (uint2*)w2_q);

    // 2) LN1 -> src2h (fp16), qkh = LN + pos (fp16)
    ln_kernel<true><<<MROWS, 256>>>(src, ln1_g, ln1_b, pos, src2h, qkh);

    // 3) fused Q+K projection: M=4096, N=2048, K=1024 (q cols scaled 1/8)
    hgemm<<<dim3(2048 / 128, MROWS / 128), 256>>>(
        qkh, win_q, nullptr, qk2, nullptr, nullptr, alpha_in,
        D_DIM, D_DIM, D_DIM, 2048, 0.125f, 1.0f, 1024, 0);

    //    V projection
    hgemm<<<dim3(D_DIM / 128, MROWS / 128), 256>>>(
        src2h, win_q + 2 * D_DIM * D_DIM, nullptr, vh, nullptr, nullptr,
        alpha_in, D_DIM, D_DIM, D_DIM, D_DIM, 1.0f, 1.0f, 1 << 30, 0);

    // 4) fused attention -> ctxh
    flash_kernel<<<dim3(S_DIM / 128, NBH), 256, FL_SMEM>>>(qk2, vh, ctxh);

    // 5) res = src + ctx @ Wout^T * alpha_out   (fp32 out)
    hgemm<<<dim3(D_DIM / 128, MROWS / 128), 256>>>(
        ctxh, wout_q, res, nullptr, nullptr, src, alpha_out,
        D_DIM, D_DIM, D_DIM, D_DIM, 1.0f, 1.0f, 1 << 30, 0);

    // 6) LN2 -> src2bh (fp16)
    ln_kernel<false><<<MROWS, 256>>>(res, ln2_g, ln2_b, nullptr, src2bh, nullptr);

    // 7) FFN1: h = relu(src2b @ W1^T * alpha1 + b1)  -> fp16
    hgemm<<<dim3(DFF_DIM / 128, MROWS / 128), 256>>>(
        src2bh, w1_q, nullptr, hbufh, b1, nullptr, alpha1,
        D_DIM, D_DIM, D_DIM, DFF_DIM, 1.0f, 1.0f, 1 << 30, 1);

    // 8) FFN2: out = res + h @ W2^T * alpha2 + b2  (fp32 out, K=4096)
    hgemm<<<dim3(D_DIM / 128, MROWS / 128), 256>>>(
        hbufh, w2_q, out, nullptr, b2, res, alpha2,
        DFF_DIM, DFF_DIM, DFF_DIM, D_DIM, 1.0f, 1.0f, 1 << 30, 0);
}

// round 9
// speedup vs baseline: 1.1761x; 1.1761x over previous
#include <cuda_runtime.h>
#include <cuda_fp16.h>
#include <cstdint>

// ---------------------------------------------------------------------------
// TransformerEncoderLayer  S=1024 B=4 D=1024 H=16 HD=64 DFF=4096, LSQ 4-bit
// Round 9: round-7 config + __launch_bounds__(128,3) on hgemm (cap 170 regs
// -> 3 CTAs/SM = 12 warps/SM, keeping the 64x64 warp tile). Single change
// vs round 7 for attribution.
// ---------------------------------------------------------------------------

#define S_DIM   1024
#define B_DIM   4
#define D_DIM   1024
#define H_DIM   16
#define HD_DIM  64
#define DFF_DIM 4096
#define MROWS   (S_DIM * B_DIM)        // 4096 token rows
#define NBH     (B_DIM * H_DIM)        // 64 batch*head

// ---------------- scratch (no cudaMalloc allowed) ----------------
__device__ __align__(16) __half g_win_q [3 * D_DIM * D_DIM];
__device__ __align__(16) __half g_wout_q[D_DIM * D_DIM];
__device__ __align__(16) __half g_w1_q  [DFF_DIM * D_DIM];
__device__ __align__(16) __half g_w2_q  [(size_t)D_DIM * DFF_DIM];
__device__ __align__(16) __half g_src2h [MROWS * D_DIM];
__device__ __align__(16) __half g_qkh   [MROWS * D_DIM];
__device__ __align__(16) __half g_qk2   [(size_t)MROWS * 2048];  // q|k fused
__device__ __align__(16) __half g_vh    [MROWS * D_DIM];
__device__ __align__(16) __half g_ctxh  [MROWS * D_DIM];
__device__ __align__(16) float  g_res   [MROWS * D_DIM];
__device__ __align__(16) __half g_src2bh[MROWS * D_DIM];
__device__ __align__(16) __half g_hbufh [(size_t)MROWS * DFF_DIM];

// ---------------- PTX helpers ----------------
__device__ __forceinline__ uint32_t smem_u32(const void* p) {
    return (uint32_t)__cvta_generic_to_shared(p);
}
__device__ __forceinline__ void cp16(void* smem, const void* g) {
    asm volatile("cp.async.cg.shared.global [%0], [%1], 16;"
                 :: "r"(smem_u32(smem)), "l"(g));
}
__device__ __forceinline__ void cp_commit() {
    asm volatile("cp.async.commit_group;");
}
template <int N>
__device__ __forceinline__ void cp_wait() {
    asm volatile("cp.async.wait_group %0;" :: "n"(N));
}
__device__ __forceinline__ void ldsm4(unsigned* r, const void* p) {
    unsigned a = smem_u32(p);
    asm volatile("ldmatrix.sync.aligned.m8n8.x4.shared.b16 {%0,%1,%2,%3}, [%4];"
                 : "=r"(r[0]), "=r"(r[1]), "=r"(r[2]), "=r"(r[3]) : "r"(a));
}
__device__ __forceinline__ void ldsm4t(unsigned* r, const void* p) {
    unsigned a = smem_u32(p);
    asm volatile("ldmatrix.sync.aligned.m8n8.x4.trans.shared.b16 {%0,%1,%2,%3}, [%4];"
                 : "=r"(r[0]), "=r"(r[1]), "=r"(r[2]), "=r"(r[3]) : "r"(a));
}
__device__ __forceinline__ void mma16816(float* d, const unsigned* a,
                                         unsigned b0, unsigned b1) {
    asm volatile(
        "mma.sync.aligned.m16n8k16.row.col.f32.f16.f16.f32 "
        "{%0,%1,%2,%3}, {%4,%5,%6,%7}, {%8,%9}, {%0,%1,%2,%3};\n"
        : "+f"(d[0]), "+f"(d[1]), "+f"(d[2]), "+f"(d[3])
        : "r"(a[0]), "r"(a[1]), "r"(a[2]), "r"(a[3]), "r"(b0), "r"(b1));
}
__device__ __forceinline__ unsigned packh2(float x, float y) {
    __half2 h = __floats2half2_rn(x, y);
    return *reinterpret_cast<unsigned*>(&h);
}

// ---------------- fused LSQ quant (all 4 weight mats, 1 launch) -------------
__global__ void __launch_bounds__(256)
quant4_kernel(const float4* __restrict__ w0, const float4* __restrict__ w1,
              const float4* __restrict__ w2, const float4* __restrict__ w3,
              const float* __restrict__ a0, const float* __restrict__ a1,
              const float* __restrict__ a2, const float* __restrict__ a3,
              uint2* __restrict__ o0, uint2* __restrict__ o1,
              uint2* __restrict__ o2, uint2* __restrict__ o3) {
    int j = blockIdx.x * blockDim.x + threadIdx.x;
    const float4* w; const float* a; uint2* o;
    if (j < 786432)                     { w = w0; a = a0; o = o0; }
    else if ((j -= 786432) < 262144)    { w = w1; a = a1; o = o1; }
    else if ((j -= 262144) < 1048576)   { w = w2; a = a2; o = o2; }
    else { j -= 1048576;                  w = w3; a = a3; o = o3; }
    const float ia = 1.0f / __ldg(a);
    const float4 v = w[j];
    const float q0 = rintf(fminf(fmaxf(v.x * ia, -8.0f), 7.0f));
    const float q1 = rintf(fminf(fmaxf(v.y * ia, -8.0f), 7.0f));
    const float q2 = rintf(fminf(fmaxf(v.z * ia, -8.0f), 7.0f));
    const float q3 = rintf(fminf(fmaxf(v.w * ia, -8.0f), 7.0f));
    o[j] = make_uint2(packh2(q0, q1), packh2(q2, q3));
}

// ---------------- LayerNorm (fp32 math, fp16 outputs, float4 I/O) -----------
template <bool WRITE_QK>
__global__ void __launch_bounds__(256)
ln_kernel(const float* __restrict__ x, const float* __restrict__ gam,
          const float* __restrict__ bet, const float* __restrict__ pos,
          __half* __restrict__ out, __half* __restrict__ qk) {
    __shared__ float red[256];
    const int row = blockIdx.x;
    const int t = threadIdx.x;
    const size_t rb = (size_t)row * D_DIM;

    const float4 xv = *reinterpret_cast<const float4*>(x + rb + 4 * t);
    float s = xv.x + xv.y + xv.z + xv.w;
    red[t] = s; __syncthreads();
    for (int off = 128; off > 0; off >>= 1) {
        if (t < off) red[t] += red[t + off];
        __syncthreads();
    }
    const float mean = red[0] * (1.0f / D_DIM);
    __syncthreads();

    const float d0 = xv.x - mean, d1 = xv.y - mean,
                d2 = xv.z - mean, d3 = xv.w - mean;
    red[t] = d0 * d0 + d1 * d1 + d2 * d2 + d3 * d3;
    __syncthreads();
    for (int off = 128; off > 0; off >>= 1) {
        if (t < off) red[t] += red[t + off];
        __syncthreads();
    }
    const float rstd = rsqrtf(red[0] * (1.0f / D_DIM) + 1e-5f);

    const float4 gv = *reinterpret_cast<const float4*>(gam + 4 * t);
    const float4 bv = *reinterpret_cast<const float4*>(bet + 4 * t);
    const float y0 = d0 * rstd * gv.x + bv.x;
    const float y1 = d1 * rstd * gv.y + bv.y;
    const float y2 = d2 * rstd * gv.z + bv.z;
    const float y3 = d3 * rstd * gv.w + bv.w;
    *reinterpret_cast<uint2*>(out + rb + 4 * t) =
        make_uint2(packh2(y0, y1), packh2(y2, y3));
    if (WRITE_QK) {
        const float4 pv = *reinterpret_cast<const float4*>(pos + rb + 4 * t);
        *reinterpret_cast<uint2*>(qk + rb + 4 * t) =
            make_uint2(packh2(y0 + pv.x, y1 + pv.y),
                       packh2(y2 + pv.z, y3 + pv.w));
    }
}

// ---------------- pipelined fp16 NT GEMM (4 warps, 64x64, 3 CTAs/SM) --------
// C[m,n] = s(col)*alpha * sum_k A[m,k]*B[n,k]  (+bias, +resid fp32, relu)
// BM=BN=128, BK=32, 128 threads (4 warps 2x2, warp tile 64x64), 2-stage.
// launch_bounds(128,3): cap 170 regs -> 3 CTAs/SM = 12 warps/SM.
__global__ void __launch_bounds__(128, 3)
hgemm(const __half* __restrict__ A, const __half* __restrict__ Bm,
      float* __restrict__ C32, __half* __restrict__ C16,
      const float* __restrict__ bias, const float* __restrict__ resid,
      const float* __restrict__ alphaPtr,
      int K, int lda, int ldb, int ldc,
      float scaleLo, float scaleHi, int splitCol, int relu) {
    __shared__ alignas(16) __half As[2][128][40];
    __shared__ alignas(16) __half Bs[2][128][40];

    const int bm = blockIdx.y * 128;
    const int bn = blockIdx.x * 128;
    const int tid = threadIdx.x;
    const int wid = tid >> 5;
    const int lane = tid & 31;
    const int wm = (wid & 1) * 64;
    const int wn = (wid >> 1) * 64;
    const int g = lane >> 2, tg = lane & 3;
    const int lrow = lane & 15;
    const int lcol = (lane >> 4) * 8;

    float acc[4][8][4];
#pragma unroll
    for (int i = 0; i < 4; i++)
#pragma unroll
        for (int j = 0; j < 8; j++)
#pragma unroll
            for (int e = 0; e < 4; e++) acc[i][j][e] = 0.f;

    const int TILES = K >> 5;

#define LOAD_TILE(kt, st)                                                     \
    {                                                                         \
        const int k0 = (kt) << 5;                                             \
        _Pragma("unroll")                                                     \
        for (int t = 0; t < 4; t++) {                                         \
            const int i = tid + t * 128;                                      \
            const int r = i >> 2, c = (i & 3) * 8;                            \
            cp16(&As[st][r][c], A + (long)(bm + r) * lda + k0 + c);           \
            cp16(&Bs[st][r][c], Bm + (long)(bn + r) * ldb + k0 + c);          \
        }                                                                     \
    }

    LOAD_TILE(0, 0);
    cp_commit();

    for (int kt = 0; kt < TILES; ++kt) {
        if (kt + 1 < TILES) LOAD_TILE(kt + 1, (kt + 1) & 1);
        cp_commit();
        cp_wait<1>();
        __syncthreads();

        const int st = kt & 1;
#pragma unroll
        for (int ks = 0; ks < 32; ks += 16) {
            unsigned a[4][4];
#pragma unroll
            for (int mt = 0; mt < 4; mt++)
                ldsm4(a[mt], &As[st][wm + mt * 16 + lrow][ks + lcol]);
            unsigned b[8][2];
#pragma unroll
            for (int i = 0; i < 4; i++) {
                unsigned b4[4];
                ldsm4(b4, &Bs[st][wn + i * 16 + lrow][ks + lcol]);
                b[2 * i][0] = b4[0]; b[2 * i][1] = b4[2];
                b[2 * i + 1][0] = b4[1]; b[2 * i + 1][1] = b4[3];
            }
#pragma unroll
            for (int mt = 0; mt < 4; mt++)
#pragma unroll
                for (int nt = 0; nt < 8; nt++)
                    mma16816(acc[mt][nt], a[mt], b[nt][0], b[nt][1]);
        }
        __syncthreads();
    }
#undef LOAD_TILE

    const float al = alphaPtr ? __ldg(alphaPtr) : 1.0f;
#pragma unroll
    for (int mt = 0; mt < 4; mt++) {
#pragma unroll
        for (int nt = 0; nt < 8; nt++) {
            const int row0 = bm + wm + mt * 16 + g;
            const int col0 = bn + wn + nt * 8 + tg * 2;
            const float sc = (col0 < splitCol ? scaleLo : scaleHi) * al;
            float bx = 0.f, by = 0.f;
            if (bias) {
                const float2 bb = *reinterpret_cast<const float2*>(&bias[col0]);
                bx = bb.x; by = bb.y;
            }
#pragma unroll
            for (int h = 0; h < 2; ++h) {
                const int row = row0 + h * 8;
                float v0 = acc[mt][nt][2 * h] * sc + bx;
                float v1 = acc[mt][nt][2 * h + 1] * sc + by;
                if (resid) {
                    const float2 rr = *reinterpret_cast<const float2*>(
                        &resid[(long)row * ldc + col0]);
                    v0 += rr.x; v1 += rr.y;
                }
                if (relu) { v0 = fmaxf(v0, 0.f); v1 = fmaxf(v1, 0.f); }
                if (C32)
                    *reinterpret_cast<float2*>(&C32[(long)row * ldc + col0]) =
                        make_float2(v0, v1);
                if (C16)
                    *reinterpret_cast<__half2*>(&C16[(long)row * ldc + col0]) =
                        __floats2half2_rn(v0, v1);
            }
        }
    }
}

// ---------------- fused flash attention (mma.sync) ----------------
// grid (8, 64): blockIdx.x = q-tile (128 rows), blockIdx.y = z = b*16+h.
// 256 threads = 8 warps; warp handles 16 q rows. Q pre-scaled by 1/8.
// Q/K in qk2: elem (s,b,h,d) = s*8192 + b*2048 + h*64 + d (K at +1024).
// V/O: s*4096 + b*1024 + h*64 + d.
#define FL_SMEM (3 * 128 * 72 * 2)
__global__ void __launch_bounds__(256)
flash_kernel(const __half* __restrict__ QK2, const __half* __restrict__ Vg,
             __half* __restrict__ O) {
    extern __shared__ __half fsm[];
    __half (*Qs)[72] = reinterpret_cast<__half(*)[72]>(fsm);
    __half (*Ks)[72] = reinterpret_cast<__half(*)[72]>(fsm + 128 * 72);
    __half (*Vs)[72] = reinterpret_cast<__half(*)[72]>(fsm + 2 * 128 * 72);

    const int z = blockIdx.y;
    const int qt = blockIdx.x;
    const int tid = threadIdx.x;
    const int wid = tid >> 5, lane = tid & 31;
    const int g = lane >> 2, tg = lane & 3;
    const int lrow = lane & 15, lcol = (lane >> 4) * 8;
    const long qOff = (long)(z >> 4) * 2048 + (z & 15) * 64;
    const long vOff = (long)z * 64;
    const int wq = wid * 16;

    for (int i = tid; i < 128 * 8; i += 256) {
        const int r = i >> 3, c = (i & 7) * 8;
        *reinterpret_cast<int4*>(&Qs[r][c]) =
            *reinterpret_cast<const int4*>(QK2 + qOff + (long)(qt * 128 + r) * 8192 + c);
    }

    float accO[8][4];
#pragma unroll
    for (int i = 0; i < 8; i++)
#pragma unroll
        for (int e = 0; e < 4; e++) accO[i][e] = 0.f;
    float mrow[2] = {-1e30f, -1e30f};
    float lrow_[2] = {0.f, 0.f};

    for (int t = 0; t < 8; ++t) {
        __syncthreads();
        for (int i = tid; i < 128 * 8; i += 256) {
            const int r = i >> 3, c = (i & 7) * 8;
            *reinterpret_cast<int4*>(&Ks[r][c]) =
                *reinterpret_cast<const int4*>(QK2 + 1024 + qOff +
                                               (long)(t * 128 + r) * 8192 + c);
            *reinterpret_cast<int4*>(&Vs[r][c]) =
                *reinterpret_cast<const int4*>(Vg + vOff +
                                               (long)(t * 128 + r) * 4096 + c);
        }
        __syncthreads();

        float accS[16][4];
#pragma unroll
        for (int i = 0; i < 16; i++)
#pragma unroll
            for (int e = 0; e < 4; e++) accS[i][e] = 0.f;

#pragma unroll
        for (int kc = 0; kc < 4; ++kc) {
            unsigned a[4];
            ldsm4(a, &Qs[wq + lrow][kc * 16 + lcol]);
#pragma unroll
            for (int i = 0; i < 8; ++i) {
                unsigned b4[4];
                ldsm4(b4, &Ks[i * 16 + lrow][kc * 16 + lcol]);
                mma16816(accS[2 * i], a, b4[0], b4[2]);
                mma16816(accS[2 * i + 1], a, b4[1], b4[3]);
            }
        }

#pragma unroll
        for (int e = 0; e < 2; ++e) {
            float rmax = -1e30f;
#pragma unroll
            for (int nt = 0; nt < 16; nt++)
                rmax = fmaxf(rmax, fmaxf(accS[nt][2 * e], accS[nt][2 * e + 1]));
            rmax = fmaxf(rmax, __shfl_xor_sync(0xffffffffu, rmax, 1));
            rmax = fmaxf(rmax, __shfl_xor_sync(0xffffffffu, rmax, 2));
            const float mnew = fmaxf(mrow[e], rmax);
            const float corr = __expf(mrow[e] - mnew);
            mrow[e] = mnew;
            lrow_[e] *= corr;
#pragma unroll
            for (int nt = 0; nt < 8; nt++) {
                accO[nt][2 * e] *= corr;
                accO[nt][2 * e + 1] *= corr;
            }
            float sum = 0.f;
#pragma unroll
            for (int nt = 0; nt < 16; nt++) {
                const float p0 = __expf(accS[nt][2 * e] - mnew);
                const float p1 = __expf(accS[nt][2 * e + 1] - mnew);
                accS[nt][2 * e] = p0; accS[nt][2 * e + 1] = p1;
                sum += p0 + p1;
            }
            lrow_[e] += sum;
        }

#pragma unroll
        for (int j = 0; j < 8; ++j) {
            unsigned aP[4];
            aP[0] = packh2(accS[2 * j][0], accS[2 * j][1]);
            aP[1] = packh2(accS[2 * j][2], accS[2 * j][3]);
            aP[2] = packh2(accS[2 * j + 1][0], accS[2 * j + 1][1]);
            aP[3] = packh2(accS[2 * j + 1][2], accS[2 * j + 1][3]);
#pragma unroll
            for (int i = 0; i < 4; ++i) {
                unsigned b4[4];
                ldsm4t(b4, &Vs[j * 16 + (lane & 7) + ((lane >> 3) & 1) * 8]
                           [i * 16 + (lane >> 4) * 8]);
                mma16816(accO[2 * i], aP, b4[0], b4[1]);
                mma16816(accO[2 * i + 1], aP, b4[2], b4[3]);
            }
        }
    }

#pragma unroll
    for (int e = 0; e < 2; ++e) {
        float l = lrow_[e];
        l += __shfl_xor_sync(0xffffffffu, l, 1);
        l += __shfl_xor_sync(0xffffffffu, l, 2);
        const float inv = 1.0f / l;
        const int r = qt * 128 + wq + g + 8 * e;
#pragma unroll
        for (int nt = 0; nt < 8; nt++) {
            __half2 h = __floats2half2_rn(accO[nt][2 * e] * inv,
                                          accO[nt][2 * e + 1] * inv);
            *reinterpret_cast<__half2*>(O + (long)r * 4096 + vOff + nt * 8 + tg * 2) = h;
        }
    }
}

// ---------------------------------------------------------------------------
extern "C" void kernel_launch(void* const* d_in, const int* in_sizes, int n_in,
                              void* d_out, int out_size) {
    const float* src        = (const float*)d_in[0];
    const float* pos        = (const float*)d_in[1];
    const float* in_proj_w  = (const float*)d_in[2];
    const float* alpha_in   = (const float*)d_in[3];
    const float* out_proj_w = (const float*)d_in[4];
    const float* alpha_out  = (const float*)d_in[5];
    const float* w1         = (const float*)d_in[6];
    const float* b1         = (const float*)d_in[7];
    const float* alpha1     = (const float*)d_in[8];
    const float* w2         = (const float*)d_in[9];
    const float* b2         = (const float*)d_in[10];
    const float* alpha2     = (const float*)d_in[11];
    const float* ln1_g      = (const float*)d_in[12];
    const float* ln1_b      = (const float*)d_in[13];
    const float* ln2_g      = (const float*)d_in[14];
    const float* ln2_b      = (const float*)d_in[15];
    float* out = (float*)d_out;

    __half *win_q, *wout_q, *w1_q, *w2_q, *src2h, *qkh, *qk2, *vh;
    __half *ctxh, *src2bh, *hbufh;
    float *res;
    cudaGetSymbolAddress((void**)&win_q,  g_win_q);
    cudaGetSymbolAddress((void**)&wout_q, g_wout_q);
    cudaGetSymbolAddress((void**)&w1_q,   g_w1_q);
    cudaGetSymbolAddress((void**)&w2_q,   g_w2_q);
    cudaGetSymbolAddress((void**)&src2h,  g_src2h);
    cudaGetSymbolAddress((void**)&qkh,    g_qkh);
    cudaGetSymbolAddress((void**)&qk2,    g_qk2);
    cudaGetSymbolAddress((void**)&vh,     g_vh);
    cudaGetSymbolAddress((void**)&ctxh,   g_ctxh);
    cudaGetSymbolAddress((void**)&res,    g_res);
    cudaGetSymbolAddress((void**)&src2bh, g_src2bh);
    cudaGetSymbolAddress((void**)&hbufh,  g_hbufh);

    cudaFuncSetAttribute(flash_kernel,
                         cudaFuncAttributeMaxDynamicSharedMemorySize, FL_SMEM);

    // 1) quantize all weights (single launch)
    quant4_kernel<<<12288, 256>>>(
        (const float4*)in_proj_w, (const float4*)out_proj_w,
        (const float4*)w1, (const float4*)w2,
        alpha_in, alpha_out, alpha1, alpha2,
        (uint2*)win_q, (uint2*)wout_q, (uint2*)w1_q, (uint2*)w2_q);

    // 2) LN1 -> src2h (fp16), qkh = LN + pos (fp16)
    ln_kernel<true><<<MROWS, 256>>>(src, ln1_g, ln1_b, pos, src2h, qkh);

    // 3) fused Q+K projection: M=4096, N=2048, K=1024 (q cols scaled 1/8)
    hgemm<<<dim3(2048 / 128, MROWS / 128), 128>>>(
        qkh, win_q, nullptr, qk2, nullptr, nullptr, alpha_in,
        D_DIM, D_DIM, D_DIM, 2048, 0.125f, 1.0f, 1024, 0);

    //    V projection
    hgemm<<<dim3(D_DIM / 128, MROWS / 128), 128>>>(
        src2h, win_q + 2 * D_DIM * D_DIM, nullptr, vh, nullptr, nullptr,
        alpha_in, D_DIM, D_DIM, D_DIM, D_DIM, 1.0f, 1.0f, 1 << 30, 0);

    // 4) fused attention -> ctxh
    flash_kernel<<<dim3(S_DIM / 128, NBH), 256, FL_SMEM>>>(qk2, vh, ctxh);

    // 5) res = src + ctx @ Wout^T * alpha_out   (fp32 out)
    hgemm<<<dim3(D_DIM / 128, MROWS / 128), 128>>>(
        ctxh, wout_q, res, nullptr, nullptr, src, alpha_out,
        D_DIM, D_DIM, D_DIM, D_DIM, 1.0f, 1.0f, 1 << 30, 0);

    // 6) LN2 -> src2bh (fp16)
    ln_kernel<false><<<MROWS, 256>>>(res, ln2_g, ln2_b, nullptr, src2bh, nullptr);

    // 7) FFN1: h = relu(src2b @ W1^T * alpha1 + b1)  -> fp16
    hgemm<<<dim3(DFF_DIM / 128, MROWS / 128), 128>>>(
        src2bh, w1_q, nullptr, hbufh, b1, nullptr, alpha1,
        D_DIM, D_DIM, D_DIM, DFF_DIM, 1.0f, 1.0f, 1 << 30, 1);

    // 8) FFN2: out = res + h @ W2^T * alpha2 + b2  (fp32 out, K=4096)
    hgemm<<<dim3(D_DIM / 128, MROWS / 128), 128>>>(
        hbufh, w2_q, out, nullptr, b2, res, alpha2,
        DFF_DIM, DFF_DIM, DFF_DIM, D_DIM, 1.0f, 1.0f, 1 << 30, 0);
}

// round 10
// speedup vs baseline: 1.2309x; 1.0466x over previous
#include <cuda_runtime.h>
#include <cuda_fp16.h>
#include <cstdint>

// ---------------------------------------------------------------------------
// TransformerEncoderLayer  S=1024 B=4 D=1024 H=16 HD=64 DFF=4096, LSQ 4-bit
// Round 10: hgemm BK 32 -> 64 (halves barriers/cp-waits, 128 MMAs per
// inter-barrier region). Dynamic smem 73.7KB/CTA, 2-stage, 4 warps 64x64.
// Single change vs round 9.
// ---------------------------------------------------------------------------

#define S_DIM   1024
#define B_DIM   4
#define D_DIM   1024
#define H_DIM   16
#define HD_DIM  64
#define DFF_DIM 4096
#define MROWS   (S_DIM * B_DIM)        // 4096 token rows
#define NBH     (B_DIM * H_DIM)        // 64 batch*head

// ---------------- scratch (no cudaMalloc allowed) ----------------
__device__ __align__(16) __half g_win_q [3 * D_DIM * D_DIM];
__device__ __align__(16) __half g_wout_q[D_DIM * D_DIM];
__device__ __align__(16) __half g_w1_q  [DFF_DIM * D_DIM];
__device__ __align__(16) __half g_w2_q  [(size_t)D_DIM * DFF_DIM];
__device__ __align__(16) __half g_src2h [MROWS * D_DIM];
__device__ __align__(16) __half g_qkh   [MROWS * D_DIM];
__device__ __align__(16) __half g_qk2   [(size_t)MROWS * 2048];  // q|k fused
__device__ __align__(16) __half g_vh    [MROWS * D_DIM];
__device__ __align__(16) __half g_ctxh  [MROWS * D_DIM];
__device__ __align__(16) float  g_res   [MROWS * D_DIM];
__device__ __align__(16) __half g_src2bh[MROWS * D_DIM];
__device__ __align__(16) __half g_hbufh [(size_t)MROWS * DFF_DIM];

// ---------------- PTX helpers ----------------
__device__ __forceinline__ uint32_t smem_u32(const void* p) {
    return (uint32_t)__cvta_generic_to_shared(p);
}
__device__ __forceinline__ void cp16(void* smem, const void* g) {
    asm volatile("cp.async.cg.shared.global [%0], [%1], 16;"
                 :: "r"(smem_u32(smem)), "l"(g));
}
__device__ __forceinline__ void cp_commit() {
    asm volatile("cp.async.commit_group;");
}
template <int N>
__device__ __forceinline__ void cp_wait() {
    asm volatile("cp.async.wait_group %0;" :: "n"(N));
}
__device__ __forceinline__ void ldsm4(unsigned* r, const void* p) {
    unsigned a = smem_u32(p);
    asm volatile("ldmatrix.sync.aligned.m8n8.x4.shared.b16 {%0,%1,%2,%3}, [%4];"
                 : "=r"(r[0]), "=r"(r[1]), "=r"(r[2]), "=r"(r[3]) : "r"(a));
}
__device__ __forceinline__ void ldsm4t(unsigned* r, const void* p) {
    unsigned a = smem_u32(p);
    asm volatile("ldmatrix.sync.aligned.m8n8.x4.trans.shared.b16 {%0,%1,%2,%3}, [%4];"
                 : "=r"(r[0]), "=r"(r[1]), "=r"(r[2]), "=r"(r[3]) : "r"(a));
}
__device__ __forceinline__ void mma16816(float* d, const unsigned* a,
                                         unsigned b0, unsigned b1) {
    asm volatile(
        "mma.sync.aligned.m16n8k16.row.col.f32.f16.f16.f32 "
        "{%0,%1,%2,%3}, {%4,%5,%6,%7}, {%8,%9}, {%0,%1,%2,%3};\n"
        : "+f"(d[0]), "+f"(d[1]), "+f"(d[2]), "+f"(d[3])
        : "r"(a[0]), "r"(a[1]), "r"(a[2]), "r"(a[3]), "r"(b0), "r"(b1));
}
__device__ __forceinline__ unsigned packh2(float x, float y) {
    __half2 h = __floats2half2_rn(x, y);
    return *reinterpret_cast<unsigned*>(&h);
}

// ---------------- fused LSQ quant (all 4 weight mats, 1 launch) -------------
__global__ void __launch_bounds__(256)
quant4_kernel(const float4* __restrict__ w0, const float4* __restrict__ w1,
              const float4* __restrict__ w2, const float4* __restrict__ w3,
              const float* __restrict__ a0, const float* __restrict__ a1,
              const float* __restrict__ a2, const float* __restrict__ a3,
              uint2* __restrict__ o0, uint2* __restrict__ o1,
              uint2* __restrict__ o2, uint2* __restrict__ o3) {
    int j = blockIdx.x * blockDim.x + threadIdx.x;
    const float4* w; const float* a; uint2* o;
    if (j < 786432)                     { w = w0; a = a0; o = o0; }
    else if ((j -= 786432) < 262144)    { w = w1; a = a1; o = o1; }
    else if ((j -= 262144) < 1048576)   { w = w2; a = a2; o = o2; }
    else { j -= 1048576;                  w = w3; a = a3; o = o3; }
    const float ia = 1.0f / __ldg(a);
    const float4 v = w[j];
    const float q0 = rintf(fminf(fmaxf(v.x * ia, -8.0f), 7.0f));
    const float q1 = rintf(fminf(fmaxf(v.y * ia, -8.0f), 7.0f));
    const float q2 = rintf(fminf(fmaxf(v.z * ia, -8.0f), 7.0f));
    const float q3 = rintf(fminf(fmaxf(v.w * ia, -8.0f), 7.0f));
    o[j] = make_uint2(packh2(q0, q1), packh2(q2, q3));
}

// ---------------- LayerNorm (fp32 math, fp16 outputs, float4 I/O) -----------
template <bool WRITE_QK>
__global__ void __launch_bounds__(256)
ln_kernel(const float* __restrict__ x, const float* __restrict__ gam,
          const float* __restrict__ bet, const float* __restrict__ pos,
          __half* __restrict__ out, __half* __restrict__ qk) {
    __shared__ float red[256];
    const int row = blockIdx.x;
    const int t = threadIdx.x;
    const size_t rb = (size_t)row * D_DIM;

    const float4 xv = *reinterpret_cast<const float4*>(x + rb + 4 * t);
    float s = xv.x + xv.y + xv.z + xv.w;
    red[t] = s; __syncthreads();
    for (int off = 128; off > 0; off >>= 1) {
        if (t < off) red[t] += red[t + off];
        __syncthreads();
    }
    const float mean = red[0] * (1.0f / D_DIM);
    __syncthreads();

    const float d0 = xv.x - mean, d1 = xv.y - mean,
                d2 = xv.z - mean, d3 = xv.w - mean;
    red[t] = d0 * d0 + d1 * d1 + d2 * d2 + d3 * d3;
    __syncthreads();
    for (int off = 128; off > 0; off >>= 1) {
        if (t < off) red[t] += red[t + off];
        __syncthreads();
    }
    const float rstd = rsqrtf(red[0] * (1.0f / D_DIM) + 1e-5f);

    const float4 gv = *reinterpret_cast<const float4*>(gam + 4 * t);
    const float4 bv = *reinterpret_cast<const float4*>(bet + 4 * t);
    const float y0 = d0 * rstd * gv.x + bv.x;
    const float y1 = d1 * rstd * gv.y + bv.y;
    const float y2 = d2 * rstd * gv.z + bv.z;
    const float y3 = d3 * rstd * gv.w + bv.w;
    *reinterpret_cast<uint2*>(out + rb + 4 * t) =
        make_uint2(packh2(y0, y1), packh2(y2, y3));
    if (WRITE_QK) {
        const float4 pv = *reinterpret_cast<const float4*>(pos + rb + 4 * t);
        *reinterpret_cast<uint2*>(qk + rb + 4 * t) =
            make_uint2(packh2(y0 + pv.x, y1 + pv.y),
                       packh2(y2 + pv.z, y3 + pv.w));
    }
}

// ---------------- pipelined fp16 NT GEMM (4 warps, 64x64, BK=64) ------------
// C[m,n] = s(col)*alpha * sum_k A[m,k]*B[n,k]  (+bias, +resid fp32, relu)
// BM=BN=128, BK=64, 128 threads (4 warps 2x2, warp tile 64x64), 2-stage,
// dynamic smem 73728B/CTA, launch_bounds(128,3).
#define HG_PITCH 72
#define HG_STAGE ((128 + 128) * HG_PITCH)        // halves per stage
#define HG_SMEM  (2 * HG_STAGE * 2)              // bytes = 73728
__global__ void __launch_bounds__(128, 3)
hgemm(const __half* __restrict__ A, const __half* __restrict__ Bm,
      float* __restrict__ C32, __half* __restrict__ C16,
      const float* __restrict__ bias, const float* __restrict__ resid,
      const float* __restrict__ alphaPtr,
      int K, int lda, int ldb, int ldc,
      float scaleLo, float scaleHi, int splitCol, int relu) {
    extern __shared__ __half hsm[];

    const int bm = blockIdx.y * 128;
    const int bn = blockIdx.x * 128;
    const int tid = threadIdx.x;
    const int wid = tid >> 5;
    const int lane = tid & 31;
    const int wm = (wid & 1) * 64;
    const int wn = (wid >> 1) * 64;
    const int g = lane >> 2, tg = lane & 3;
    const int lrow = lane & 15;
    const int lcol = (lane >> 4) * 8;

    float acc[4][8][4];
#pragma unroll
    for (int i = 0; i < 4; i++)
#pragma unroll
        for (int j = 0; j < 8; j++)
#pragma unroll
            for (int e = 0; e < 4; e++) acc[i][j][e] = 0.f;

    const int TILES = K >> 6;    // chunks of 64

    // loader: per chunk, A and B are 128 rows x 64 halves (8 int4/row).
    // 1024 int4 per matrix / 128 thr = 8 iters each.
#define LOAD_TILE(kt, st)                                                     \
    {                                                                         \
        const int k0 = (kt) << 6;                                             \
        __half* sA = hsm + (st) * HG_STAGE;                                   \
        __half* sB = sA + 128 * HG_PITCH;                                     \
        _Pragma("unroll")                                                     \
        for (int t = 0; t < 8; t++) {                                         \
            const int i = tid + t * 128;                                      \
            const int r = i >> 3, c = (i & 7) * 8;                            \
            cp16(&sA[r * HG_PITCH + c], A + (long)(bm + r) * lda + k0 + c);   \
            cp16(&sB[r * HG_PITCH + c], Bm + (long)(bn + r) * ldb + k0 + c);  \
        }                                                                     \
    }

    LOAD_TILE(0, 0);
    cp_commit();

    for (int kt = 0; kt < TILES; ++kt) {
        if (kt + 1 < TILES) LOAD_TILE(kt + 1, (kt + 1) & 1);
        cp_commit();
        cp_wait<1>();
        __syncthreads();

        const __half* sA = hsm + (kt & 1) * HG_STAGE;
        const __half* sB = sA + 128 * HG_PITCH;
#pragma unroll
        for (int ks = 0; ks < 64; ks += 16) {
            unsigned a[4][4];
#pragma unroll
            for (int mt = 0; mt < 4; mt++)
                ldsm4(a[mt], &sA[(wm + mt * 16 + lrow) * HG_PITCH + ks + lcol]);
            unsigned b[8][2];
#pragma unroll
            for (int i = 0; i < 4; i++) {
                unsigned b4[4];
                ldsm4(b4, &sB[(wn + i * 16 + lrow) * HG_PITCH + ks + lcol]);
                b[2 * i][0] = b4[0]; b[2 * i][1] = b4[2];
                b[2 * i + 1][0] = b4[1]; b[2 * i + 1][1] = b4[3];
            }
#pragma unroll
            for (int mt = 0; mt < 4; mt++)
#pragma unroll
                for (int nt = 0; nt < 8; nt++)
                    mma16816(acc[mt][nt], a[mt], b[nt][0], b[nt][1]);
        }
        __syncthreads();
    }
#undef LOAD_TILE

    const float al = alphaPtr ? __ldg(alphaPtr) : 1.0f;
#pragma unroll
    for (int mt = 0; mt < 4; mt++) {
#pragma unroll
        for (int nt = 0; nt < 8; nt++) {
            const int row0 = bm + wm + mt * 16 + g;
            const int col0 = bn + wn + nt * 8 + tg * 2;
            const float sc = (col0 < splitCol ? scaleLo : scaleHi) * al;
            float bx = 0.f, by = 0.f;
            if (bias) {
                const float2 bb = *reinterpret_cast<const float2*>(&bias[col0]);
                bx = bb.x; by = bb.y;
            }
#pragma unroll
            for (int h = 0; h < 2; ++h) {
                const int row = row0 + h * 8;
                float v0 = acc[mt][nt][2 * h] * sc + bx;
                float v1 = acc[mt][nt][2 * h + 1] * sc + by;
                if (resid) {
                    const float2 rr = *reinterpret_cast<const float2*>(
                        &resid[(long)row * ldc + col0]);
                    v0 += rr.x; v1 += rr.y;
                }
                if (relu) { v0 = fmaxf(v0, 0.f); v1 = fmaxf(v1, 0.f); }
                if (C32)
                    *reinterpret_cast<float2*>(&C32[(long)row * ldc + col0]) =
                        make_float2(v0, v1);
                if (C16)
                    *reinterpret_cast<__half2*>(&C16[(long)row * ldc + col0]) =
                        __floats2half2_rn(v0, v1);
            }
        }
    }
}

// ---------------- fused flash attention (mma.sync) ----------------
// grid (8, 64): blockIdx.x = q-tile (128 rows), blockIdx.y = z = b*16+h.
// 256 threads = 8 warps; warp handles 16 q rows. Q pre-scaled by 1/8.
// Q/K in qk2: elem (s,b,h,d) = s*8192 + b*2048 + h*64 + d (K at +1024).
// V/O: s*4096 + b*1024 + h*64 + d.
#define FL_SMEM (3 * 128 * 72 * 2)
__global__ void __launch_bounds__(256)
flash_kernel(const __half* __restrict__ QK2, const __half* __restrict__ Vg,
             __half* __restrict__ O) {
    extern __shared__ __half fsm[];
    __half (*Qs)[72] = reinterpret_cast<__half(*)[72]>(fsm);
    __half (*Ks)[72] = reinterpret_cast<__half(*)[72]>(fsm + 128 * 72);
    __half (*Vs)[72] = reinterpret_cast<__half(*)[72]>(fsm + 2 * 128 * 72);

    const int z = blockIdx.y;
    const int qt = blockIdx.x;
    const int tid = threadIdx.x;
    const int wid = tid >> 5, lane = tid & 31;
    const int g = lane >> 2, tg = lane & 3;
    const int lrow = lane & 15, lcol = (lane >> 4) * 8;
    const long qOff = (long)(z >> 4) * 2048 + (z & 15) * 64;
    const long vOff = (long)z * 64;
    const int wq = wid * 16;

    for (int i = tid; i < 128 * 8; i += 256) {
        const int r = i >> 3, c = (i & 7) * 8;
        *reinterpret_cast<int4*>(&Qs[r][c]) =
            *reinterpret_cast<const int4*>(QK2 + qOff + (long)(qt * 128 + r) * 8192 + c);
    }

    float accO[8][4];
#pragma unroll
    for (int i = 0; i < 8; i++)
#pragma unroll
        for (int e = 0; e < 4; e++) accO[i][e] = 0.f;
    float mrow[2] = {-1e30f, -1e30f};
    float lrow_[2] = {0.f, 0.f};

    for (int t = 0; t < 8; ++t) {
        __syncthreads();
        for (int i = tid; i < 128 * 8; i += 256) {
            const int r = i >> 3, c = (i & 7) * 8;
            *reinterpret_cast<int4*>(&Ks[r][c]) =
                *reinterpret_cast<const int4*>(QK2 + 1024 + qOff +
                                               (long)(t * 128 + r) * 8192 + c);
            *reinterpret_cast<int4*>(&Vs[r][c]) =
                *reinterpret_cast<const int4*>(Vg + vOff +
                                               (long)(t * 128 + r) * 4096 + c);
        }
        __syncthreads();

        float accS[16][4];
#pragma unroll
        for (int i = 0; i < 16; i++)
#pragma unroll
            for (int e = 0; e < 4; e++) accS[i][e] = 0.f;

#pragma unroll
        for (int kc = 0; kc < 4; ++kc) {
            unsigned a[4];
            ldsm4(a, &Qs[wq + lrow][kc * 16 + lcol]);
#pragma unroll
            for (int i = 0; i < 8; ++i) {
                unsigned b4[4];
                ldsm4(b4, &Ks[i * 16 + lrow][kc * 16 + lcol]);
                mma16816(accS[2 * i], a, b4[0], b4[2]);
                mma16816(accS[2 * i + 1], a, b4[1], b4[3]);
            }
        }

#pragma unroll
        for (int e = 0; e < 2; ++e) {
            float rmax = -1e30f;
#pragma unroll
            for (int nt = 0; nt < 16; nt++)
                rmax = fmaxf(rmax, fmaxf(accS[nt][2 * e], accS[nt][2 * e + 1]));
            rmax = fmaxf(rmax, __shfl_xor_sync(0xffffffffu, rmax, 1));
            rmax = fmaxf(rmax, __shfl_xor_sync(0xffffffffu, rmax, 2));
            const float mnew = fmaxf(mrow[e], rmax);
            const float corr = __expf(mrow[e] - mnew);
            mrow[e] = mnew;
            lrow_[e] *= corr;
#pragma unroll
            for (int nt = 0; nt < 8; nt++) {
                accO[nt][2 * e] *= corr;
                accO[nt][2 * e + 1] *= corr;
            }
            float sum = 0.f;
#pragma unroll
            for (int nt = 0; nt < 16; nt++) {
                const float p0 = __expf(accS[nt][2 * e] - mnew);
                const float p1 = __expf(accS[nt][2 * e + 1] - mnew);
                accS[nt][2 * e] = p0; accS[nt][2 * e + 1] = p1;
                sum += p0 + p1;
            }
            lrow_[e] += sum;
        }

#pragma unroll
        for (int j = 0; j < 8; ++j) {
            unsigned aP[4];
            aP[0] = packh2(accS[2 * j][0], accS[2 * j][1]);
            aP[1] = packh2(accS[2 * j][2], accS[2 * j][3]);
            aP[2] = packh2(accS[2 * j + 1][0], accS[2 * j + 1][1]);
            aP[3] = packh2(accS[2 * j + 1][2], accS[2 * j + 1][3]);
#pragma unroll
            for (int i = 0; i < 4; ++i) {
                unsigned b4[4];
                ldsm4t(b4, &Vs[j * 16 + (lane & 7) + ((lane >> 3) & 1) * 8]
                           [i * 16 + (lane >> 4) * 8]);
                mma16816(accO[2 * i], aP, b4[0], b4[1]);
                mma16816(accO[2 * i + 1], aP, b4[2], b4[3]);
            }
        }
    }

#pragma unroll
    for (int e = 0; e < 2; ++e) {
        float l = lrow_[e];
        l += __shfl_xor_sync(0xffffffffu, l, 1);
        l += __shfl_xor_sync(0xffffffffu, l, 2);
        const float inv = 1.0f / l;
        const int r = qt * 128 + wq + g + 8 * e;
#pragma unroll
        for (int nt = 0; nt < 8; nt++) {
            __half2 h = __floats2half2_rn(accO[nt][2 * e] * inv,
                                          accO[nt][2 * e + 1] * inv);
            *reinterpret_cast<__half2*>(O + (long)r * 4096 + vOff + nt * 8 + tg * 2) = h;
        }
    }
}

// ---------------------------------------------------------------------------
extern "C" void kernel_launch(void* const* d_in, const int* in_sizes, int n_in,
                              void* d_out, int out_size) {
    const float* src        = (const float*)d_in[0];
    const float* pos        = (const float*)d_in[1];
    const float* in_proj_w  = (const float*)d_in[2];
    const float* alpha_in   = (const float*)d_in[3];
    const float* out_proj_w = (const float*)d_in[4];
    const float* alpha_out  = (const float*)d_in[5];
    const float* w1         = (const float*)d_in[6];
    const float* b1         = (const float*)d_in[7];
    const float* alpha1     = (const float*)d_in[8];
    const float* w2         = (const float*)d_in[9];
    const float* b2         = (const float*)d_in[10];
    const float* alpha2     = (const float*)d_in[11];
    const float* ln1_g      = (const float*)d_in[12];
    const float* ln1_b      = (const float*)d_in[13];
    const float* ln2_g      = (const float*)d_in[14];
    const float* ln2_b      = (const float*)d_in[15];
    float* out = (float*)d_out;

    __half *win_q, *wout_q, *w1_q, *w2_q, *src2h, *qkh, *qk2, *vh;
    __half *ctxh, *src2bh, *hbufh;
    float *res;
    cudaGetSymbolAddress((void**)&win_q,  g_win_q);
    cudaGetSymbolAddress((void**)&wout_q, g_wout_q);
    cudaGetSymbolAddress((void**)&w1_q,   g_w1_q);
    cudaGetSymbolAddress((void**)&w2_q,   g_w2_q);
    cudaGetSymbolAddress((void**)&src2h,  g_src2h);
    cudaGetSymbolAddress((void**)&qkh,    g_qkh);
    cudaGetSymbolAddress((void**)&qk2,    g_qk2);
    cudaGetSymbolAddress((void**)&vh,     g_vh);
    cudaGetSymbolAddress((void**)&ctxh,   g_ctxh);
    cudaGetSymbolAddress((void**)&res,    g_res);
    cudaGetSymbolAddress((void**)&src2bh, g_src2bh);
    cudaGetSymbolAddress((void**)&hbufh,  g_hbufh);

    cudaFuncSetAttribute(hgemm,
                         cudaFuncAttributeMaxDynamicSharedMemorySize, HG_SMEM);
    cudaFuncSetAttribute(flash_kernel,
                         cudaFuncAttributeMaxDynamicSharedMemorySize, FL_SMEM);

    // 1) quantize all weights (single launch)
    quant4_kernel<<<12288, 256>>>(
        (const float4*)in_proj_w, (const float4*)out_proj_w,
        (const float4*)w1, (const float4*)w2,
        alpha_in, alpha_out, alpha1, alpha2,
        (uint2*)win_q, (uint2*)wout_q, (uint2*)w1_q, (uint2*)w2_q);

    // 2) LN1 -> src2h (fp16), qkh = LN + pos (fp16)
    ln_kernel<true><<<MROWS, 256>>>(src, ln1_g, ln1_b, pos, src2h, qkh);

    // 3) fused Q+K projection: M=4096, N=2048, K=1024 (q cols scaled 1/8)
    hgemm<<<dim3(2048 / 128, MROWS / 128), 128, HG_SMEM>>>(
        qkh, win_q, nullptr, qk2, nullptr, nullptr, alpha_in,
        D_DIM, D_DIM, D_DIM, 2048, 0.125f, 1.0f, 1024, 0);

    //    V projection
    hgemm<<<dim3(D_DIM / 128, MROWS / 128), 128, HG_SMEM>>>(
        src2h, win_q + 2 * D_DIM * D_DIM, nullptr, vh, nullptr, nullptr,
        alpha_in, D_DIM, D_DIM, D_DIM, D_DIM, 1.0f, 1.0f, 1 << 30, 0);

    // 4) fused attention -> ctxh
    flash_kernel<<<dim3(S_DIM / 128, NBH), 256, FL_SMEM>>>(qk2, vh, ctxh);

    // 5) res = src + ctx @ Wout^T * alpha_out   (fp32 out)
    hgemm<<<dim3(D_DIM / 128, MROWS / 128), 128, HG_SMEM>>>(
        ctxh, wout_q, res, nullptr, nullptr, src, alpha_out,
        D_DIM, D_DIM, D_DIM, D_DIM, 1.0f, 1.0f, 1 << 30, 0);

    // 6) LN2 -> src2bh (fp16)
    ln_kernel<false><<<MROWS, 256>>>(res, ln2_g, ln2_b, nullptr, src2bh, nullptr);

    // 7) FFN1: h = relu(src2b @ W1^T * alpha1 + b1)  -> fp16
    hgemm<<<dim3(DFF_DIM / 128, MROWS / 128), 128, HG_SMEM>>>(
        src2bh, w1_q, nullptr, hbufh, b1, nullptr, alpha1,
        D_DIM, D_DIM, D_DIM, DFF_DIM, 1.0f, 1.0f, 1 << 30, 1);

    // 8) FFN2: out = res + h @ W2^T * alpha2 + b2  (fp32 out, K=4096)
    hgemm<<<dim3(D_DIM / 128, MROWS / 128), 128, HG_SMEM>>>(
        hbufh, w2_q, out, nullptr, b2, res, alpha2,
        DFF_DIM, DFF_DIM, DFF_DIM, D_DIM, 1.0f, 1.0f, 1 << 30, 0);
}

// round 11
// speedup vs baseline: 1.2399x; 1.0073x over previous
#include <cuda_runtime.h>
#include <cuda_fp16.h>
#include <cstdint>

// ---------------------------------------------------------------------------
// TransformerEncoderLayer  S=1024 B=4 D=1024 H=16 HD=64 DFF=4096, LSQ 4-bit
// Round 11: software-pipelined fragment loads in hgemm mainloop (ldsm for
// ks+16 issued before mma burst for ks), launch_bounds(128,2). Single
// mechanism change vs round 10 (612.7us best).
// ---------------------------------------------------------------------------

#define S_DIM   1024
#define B_DIM   4
#define D_DIM   1024
#define H_DIM   16
#define HD_DIM  64
#define DFF_DIM 4096
#define MROWS   (S_DIM * B_DIM)        // 4096 token rows
#define NBH     (B_DIM * H_DIM)        // 64 batch*head

// ---------------- scratch (no cudaMalloc allowed) ----------------
__device__ __align__(16) __half g_win_q [3 * D_DIM * D_DIM];
__device__ __align__(16) __half g_wout_q[D_DIM * D_DIM];
__device__ __align__(16) __half g_w1_q  [DFF_DIM * D_DIM];
__device__ __align__(16) __half g_w2_q  [(size_t)D_DIM * DFF_DIM];
__device__ __align__(16) __half g_src2h [MROWS * D_DIM];
__device__ __align__(16) __half g_qkh   [MROWS * D_DIM];
__device__ __align__(16) __half g_qk2   [(size_t)MROWS * 2048];  // q|k fused
__device__ __align__(16) __half g_vh    [MROWS * D_DIM];
__device__ __align__(16) __half g_ctxh  [MROWS * D_DIM];
__device__ __align__(16) float  g_res   [MROWS * D_DIM];
__device__ __align__(16) __half g_src2bh[MROWS * D_DIM];
__device__ __align__(16) __half g_hbufh [(size_t)MROWS * DFF_DIM];

// ---------------- PTX helpers ----------------
__device__ __forceinline__ uint32_t smem_u32(const void* p) {
    return (uint32_t)__cvta_generic_to_shared(p);
}
__device__ __forceinline__ void cp16(void* smem, const void* g) {
    asm volatile("cp.async.cg.shared.global [%0], [%1], 16;"
                 :: "r"(smem_u32(smem)), "l"(g));
}
__device__ __forceinline__ void cp_commit() {
    asm volatile("cp.async.commit_group;");
}
template <int N>
__device__ __forceinline__ void cp_wait() {
    asm volatile("cp.async.wait_group %0;" :: "n"(N));
}
__device__ __forceinline__ void ldsm4(unsigned* r, const void* p) {
    unsigned a = smem_u32(p);
    asm volatile("ldmatrix.sync.aligned.m8n8.x4.shared.b16 {%0,%1,%2,%3}, [%4];"
                 : "=r"(r[0]), "=r"(r[1]), "=r"(r[2]), "=r"(r[3]) : "r"(a));
}
__device__ __forceinline__ void ldsm4t(unsigned* r, const void* p) {
    unsigned a = smem_u32(p);
    asm volatile("ldmatrix.sync.aligned.m8n8.x4.trans.shared.b16 {%0,%1,%2,%3}, [%4];"
                 : "=r"(r[0]), "=r"(r[1]), "=r"(r[2]), "=r"(r[3]) : "r"(a));
}
__device__ __forceinline__ void mma16816(float* d, const unsigned* a,
                                         unsigned b0, unsigned b1) {
    asm volatile(
        "mma.sync.aligned.m16n8k16.row.col.f32.f16.f16.f32 "
        "{%0,%1,%2,%3}, {%4,%5,%6,%7}, {%8,%9}, {%0,%1,%2,%3};\n"
        : "+f"(d[0]), "+f"(d[1]), "+f"(d[2]), "+f"(d[3])
        : "r"(a[0]), "r"(a[1]), "r"(a[2]), "r"(a[3]), "r"(b0), "r"(b1));
}
__device__ __forceinline__ unsigned packh2(float x, float y) {
    __half2 h = __floats2half2_rn(x, y);
    return *reinterpret_cast<unsigned*>(&h);
}

// ---------------- fused LSQ quant (all 4 weight mats, 1 launch) -------------
__global__ void __launch_bounds__(256)
quant4_kernel(const float4* __restrict__ w0, const float4* __restrict__ w1,
              const float4* __restrict__ w2, const float4* __restrict__ w3,
              const float* __restrict__ a0, const float* __restrict__ a1,
              const float* __restrict__ a2, const float* __restrict__ a3,
              uint2* __restrict__ o0, uint2* __restrict__ o1,
              uint2* __restrict__ o2, uint2* __restrict__ o3) {
    int j = blockIdx.x * blockDim.x + threadIdx.x;
    const float4* w; const float* a; uint2* o;
    if (j < 786432)                     { w = w0; a = a0; o = o0; }
    else if ((j -= 786432) < 262144)    { w = w1; a = a1; o = o1; }
    else if ((j -= 262144) < 1048576)   { w = w2; a = a2; o = o2; }
    else { j -= 1048576;                  w = w3; a = a3; o = o3; }
    const float ia = 1.0f / __ldg(a);
    const float4 v = w[j];
    const float q0 = rintf(fminf(fmaxf(v.x * ia, -8.0f), 7.0f));
    const float q1 = rintf(fminf(fmaxf(v.y * ia, -8.0f), 7.0f));
    const float q2 = rintf(fminf(fmaxf(v.z * ia, -8.0f), 7.0f));
    const float q3 = rintf(fminf(fmaxf(v.w * ia, -8.0f), 7.0f));
    o[j] = make_uint2(packh2(q0, q1), packh2(q2, q3));
}

// ---------------- LayerNorm (fp32 math, fp16 outputs, float4 I/O) -----------
template <bool WRITE_QK>
__global__ void __launch_bounds__(256)
ln_kernel(const float* __restrict__ x, const float* __restrict__ gam,
          const float* __restrict__ bet, const float* __restrict__ pos,
          __half* __restrict__ out, __half* __restrict__ qk) {
    __shared__ float red[256];
    const int row = blockIdx.x;
    const int t = threadIdx.x;
    const size_t rb = (size_t)row * D_DIM;

    const float4 xv = *reinterpret_cast<const float4*>(x + rb + 4 * t);
    float s = xv.x + xv.y + xv.z + xv.w;
    red[t] = s; __syncthreads();
    for (int off = 128; off > 0; off >>= 1) {
        if (t < off) red[t] += red[t + off];
        __syncthreads();
    }
    const float mean = red[0] * (1.0f / D_DIM);
    __syncthreads();

    const float d0 = xv.x - mean, d1 = xv.y - mean,
                d2 = xv.z - mean, d3 = xv.w - mean;
    red[t] = d0 * d0 + d1 * d1 + d2 * d2 + d3 * d3;
    __syncthreads();
    for (int off = 128; off > 0; off >>= 1) {
        if (t < off) red[t] += red[t + off];
        __syncthreads();
    }
    const float rstd = rsqrtf(red[0] * (1.0f / D_DIM) + 1e-5f);

    const float4 gv = *reinterpret_cast<const float4*>(gam + 4 * t);
    const float4 bv = *reinterpret_cast<const float4*>(bet + 4 * t);
    const float y0 = d0 * rstd * gv.x + bv.x;
    const float y1 = d1 * rstd * gv.y + bv.y;
    const float y2 = d2 * rstd * gv.z + bv.z;
    const float y3 = d3 * rstd * gv.w + bv.w;
    *reinterpret_cast<uint2*>(out + rb + 4 * t) =
        make_uint2(packh2(y0, y1), packh2(y2, y3));
    if (WRITE_QK) {
        const float4 pv = *reinterpret_cast<const float4*>(pos + rb + 4 * t);
        *reinterpret_cast<uint2*>(qk + rb + 4 * t) =
            make_uint2(packh2(y0 + pv.x, y1 + pv.y),
                       packh2(y2 + pv.z, y3 + pv.w));
    }
}

// ---------------- pipelined fp16 NT GEMM (4 warps, 64x64, BK=64) ------------
// C[m,n] = s(col)*alpha * sum_k A[m,k]*B[n,k]  (+bias, +resid fp32, relu)
// BM=BN=128, BK=64, 128 threads (4 warps 2x2, warp tile 64x64), 2-stage,
// dynamic smem 73728B/CTA. Fragment loads double-buffered across ks-steps.
#define HG_PITCH 72
#define HG_STAGE ((128 + 128) * HG_PITCH)        // halves per stage
#define HG_SMEM  (2 * HG_STAGE * 2)              // bytes = 73728
__global__ void __launch_bounds__(128, 2)
hgemm(const __half* __restrict__ A, const __half* __restrict__ Bm,
      float* __restrict__ C32, __half* __restrict__ C16,
      const float* __restrict__ bias, const float* __restrict__ resid,
      const float* __restrict__ alphaPtr,
      int K, int lda, int ldb, int ldc,
      float scaleLo, float scaleHi, int splitCol, int relu) {
    extern __shared__ __half hsm[];

    const int bm = blockIdx.y * 128;
    const int bn = blockIdx.x * 128;
    const int tid = threadIdx.x;
    const int wid = tid >> 5;
    const int lane = tid & 31;
    const int wm = (wid & 1) * 64;
    const int wn = (wid >> 1) * 64;
    const int g = lane >> 2, tg = lane & 3;
    const int lrow = lane & 15;
    const int lcol = (lane >> 4) * 8;

    float acc[4][8][4];
#pragma unroll
    for (int i = 0; i < 4; i++)
#pragma unroll
        for (int j = 0; j < 8; j++)
#pragma unroll
            for (int e = 0; e < 4; e++) acc[i][j][e] = 0.f;

    const int TILES = K >> 6;    // chunks of 64

#define LOAD_TILE(kt, st)                                                     \
    {                                                                         \
        const int k0 = (kt) << 6;                                             \
        __half* sA = hsm + (st) * HG_STAGE;                                   \
        __half* sB = sA + 128 * HG_PITCH;                                     \
        _Pragma("unroll")                                                     \
        for (int t = 0; t < 8; t++) {                                         \
            const int i = tid + t * 128;                                      \
            const int r = i >> 3, c = (i & 7) * 8;                            \
            cp16(&sA[r * HG_PITCH + c], A + (long)(bm + r) * lda + k0 + c);   \
            cp16(&sB[r * HG_PITCH + c], Bm + (long)(bn + r) * ldb + k0 + c);  \
        }                                                                     \
    }

    // load fragments for ks-step into register buffer pb
#define LOAD_FRAG(sA, sB, ks, pb)                                             \
    {                                                                         \
        _Pragma("unroll")                                                     \
        for (int mt = 0; mt < 4; mt++)                                        \
            ldsm4(af[pb][mt],                                                 \
                  &sA[(wm + mt * 16 + lrow) * HG_PITCH + (ks) + lcol]);       \
        _Pragma("unroll")                                                     \
        for (int i = 0; i < 4; i++) {                                         \
            unsigned b4[4];                                                   \
            ldsm4(b4, &sB[(wn + i * 16 + lrow) * HG_PITCH + (ks) + lcol]);    \
            bf[pb][2 * i][0] = b4[0]; bf[pb][2 * i][1] = b4[2];               \
            bf[pb][2 * i + 1][0] = b4[1]; bf[pb][2 * i + 1][1] = b4[3];       \
        }                                                                     \
    }

    LOAD_TILE(0, 0);
    cp_commit();

    unsigned af[2][4][4];
    unsigned bf[2][8][2];

    for (int kt = 0; kt < TILES; ++kt) {
        if (kt + 1 < TILES) LOAD_TILE(kt + 1, (kt + 1) & 1);
        cp_commit();
        cp_wait<1>();
        __syncthreads();

        const __half* sA = hsm + (kt & 1) * HG_STAGE;
        const __half* sB = sA + 128 * HG_PITCH;

        LOAD_FRAG(sA, sB, 0, 0);
#pragma unroll
        for (int s = 0; s < 4; ++s) {
            const int cur = s & 1;
            if (s < 3) LOAD_FRAG(sA, sB, (s + 1) * 16, cur ^ 1);
#pragma unroll
            for (int mt = 0; mt < 4; mt++)
#pragma unroll
                for (int nt = 0; nt < 8; nt++)
                    mma16816(acc[mt][nt], af[cur][mt],
                             bf[cur][nt][0], bf[cur][nt][1]);
        }
        __syncthreads();
    }
#undef LOAD_FRAG
#undef LOAD_TILE

    const float al = alphaPtr ? __ldg(alphaPtr) : 1.0f;
#pragma unroll
    for (int mt = 0; mt < 4; mt++) {
#pragma unroll
        for (int nt = 0; nt < 8; nt++) {
            const int row0 = bm + wm + mt * 16 + g;
            const int col0 = bn + wn + nt * 8 + tg * 2;
            const float sc = (col0 < splitCol ? scaleLo : scaleHi) * al;
            float bx = 0.f, by = 0.f;
            if (bias) {
                const float2 bb = *reinterpret_cast<const float2*>(&bias[col0]);
                bx = bb.x; by = bb.y;
            }
#pragma unroll
            for (int h = 0; h < 2; ++h) {
                const int row = row0 + h * 8;
                float v0 = acc[mt][nt][2 * h] * sc + bx;
                float v1 = acc[mt][nt][2 * h + 1] * sc + by;
                if (resid) {
                    const float2 rr = *reinterpret_cast<const float2*>(
                        &resid[(long)row * ldc + col0]);
                    v0 += rr.x; v1 += rr.y;
                }
                if (relu) { v0 = fmaxf(v0, 0.f); v1 = fmaxf(v1, 0.f); }
                if (C32)
                    *reinterpret_cast<float2*>(&C32[(long)row * ldc + col0]) =
                        make_float2(v0, v1);
                if (C16)
                    *reinterpret_cast<__half2*>(&C16[(long)row * ldc + col0]) =
                        __floats2half2_rn(v0, v1);
            }
        }
    }
}

// ---------------- fused flash attention (mma.sync) ----------------
// grid (8, 64): blockIdx.x = q-tile (128 rows), blockIdx.y = z = b*16+h.
// 256 threads = 8 warps; warp handles 16 q rows. Q pre-scaled by 1/8.
// Q/K in qk2: elem (s,b,h,d) = s*8192 + b*2048 + h*64 + d (K at +1024).
// V/O: s*4096 + b*1024 + h*64 + d.
#define FL_SMEM (3 * 128 * 72 * 2)
__global__ void __launch_bounds__(256)
flash_kernel(const __half* __restrict__ QK2, const __half* __restrict__ Vg,
             __half* __restrict__ O) {
    extern __shared__ __half fsm[];
    __half (*Qs)[72] = reinterpret_cast<__half(*)[72]>(fsm);
    __half (*Ks)[72] = reinterpret_cast<__half(*)[72]>(fsm + 128 * 72);
    __half (*Vs)[72] = reinterpret_cast<__half(*)[72]>(fsm + 2 * 128 * 72);

    const int z = blockIdx.y;
    const int qt = blockIdx.x;
    const int tid = threadIdx.x;
    const int wid = tid >> 5, lane = tid & 31;
    const int g = lane >> 2, tg = lane & 3;
    const int lrow = lane & 15, lcol = (lane >> 4) * 8;
    const long qOff = (long)(z >> 4) * 2048 + (z & 15) * 64;
    const long vOff = (long)z * 64;
    const int wq = wid * 16;

    for (int i = tid; i < 128 * 8; i += 256) {
        const int r = i >> 3, c = (i & 7) * 8;
        *reinterpret_cast<int4*>(&Qs[r][c]) =
            *reinterpret_cast<const int4*>(QK2 + qOff + (long)(qt * 128 + r) * 8192 + c);
    }

    float accO[8][4];
#pragma unroll
    for (int i = 0; i < 8; i++)
#pragma unroll
        for (int e = 0; e < 4; e++) accO[i][e] = 0.f;
    float mrow[2] = {-1e30f, -1e30f};
    float lrow_[2] = {0.f, 0.f};

    for (int t = 0; t < 8; ++t) {
        __syncthreads();
        for (int i = tid; i < 128 * 8; i += 256) {
            const int r = i >> 3, c = (i & 7) * 8;
            *reinterpret_cast<int4*>(&Ks[r][c]) =
                *reinterpret_cast<const int4*>(QK2 + 1024 + qOff +
                                               (long)(t * 128 + r) * 8192 + c);
            *reinterpret_cast<int4*>(&Vs[r][c]) =
                *reinterpret_cast<const int4*>(Vg + vOff +
                                               (long)(t * 128 + r) * 4096 + c);
        }
        __syncthreads();

        float accS[16][4];
#pragma unroll
        for (int i = 0; i < 16; i++)
#pragma unroll
            for (int e = 0; e < 4; e++) accS[i][e] = 0.f;

#pragma unroll
        for (int kc = 0; kc < 4; ++kc) {
            unsigned a[4];
            ldsm4(a, &Qs[wq + lrow][kc * 16 + lcol]);
#pragma unroll
            for (int i = 0; i < 8; ++i) {
                unsigned b4[4];
                ldsm4(b4, &Ks[i * 16 + lrow][kc * 16 + lcol]);
                mma16816(accS[2 * i], a, b4[0], b4[2]);
                mma16816(accS[2 * i + 1], a, b4[1], b4[3]);
            }
        }

#pragma unroll
        for (int e = 0; e < 2; ++e) {
            float rmax = -1e30f;
#pragma unroll
            for (int nt = 0; nt < 16; nt++)
                rmax = fmaxf(rmax, fmaxf(accS[nt][2 * e], accS[nt][2 * e + 1]));
            rmax = fmaxf(rmax, __shfl_xor_sync(0xffffffffu, rmax, 1));
            rmax = fmaxf(rmax, __shfl_xor_sync(0xffffffffu, rmax, 2));
            const float mnew = fmaxf(mrow[e], rmax);
            const float corr = __expf(mrow[e] - mnew);
            mrow[e] = mnew;
            lrow_[e] *= corr;
#pragma unroll
            for (int nt = 0; nt < 8; nt++) {
                accO[nt][2 * e] *= corr;
                accO[nt][2 * e + 1] *= corr;
            }
            float sum = 0.f;
#pragma unroll
            for (int nt = 0; nt < 16; nt++) {
                const float p0 = __expf(accS[nt][2 * e] - mnew);
                const float p1 = __expf(accS[nt][2 * e + 1] - mnew);
                accS[nt][2 * e] = p0; accS[nt][2 * e + 1] = p1;
                sum += p0 + p1;
            }
            lrow_[e] += sum;
        }

#pragma unroll
        for (int j = 0; j < 8; ++j) {
            unsigned aP[4];
            aP[0] = packh2(accS[2 * j][0], accS[2 * j][1]);
            aP[1] = packh2(accS[2 * j][2], accS[2 * j][3]);
            aP[2] = packh2(accS[2 * j + 1][0], accS[2 * j + 1][1]);
            aP[3] = packh2(accS[2 * j + 1][2], accS[2 * j + 1][3]);
#pragma unroll
            for (int i = 0; i < 4; ++i) {
                unsigned b4[4];
                ldsm4t(b4, &Vs[j * 16 + (lane & 7) + ((lane >> 3) & 1) * 8]
                           [i * 16 + (lane >> 4) * 8]);
                mma16816(accO[2 * i], aP, b4[0], b4[1]);
                mma16816(accO[2 * i + 1], aP, b4[2], b4[3]);
            }
        }
    }

#pragma unroll
    for (int e = 0; e < 2; ++e) {
        float l = lrow_[e];
        l += __shfl_xor_sync(0xffffffffu, l, 1);
        l += __shfl_xor_sync(0xffffffffu, l, 2);
        const float inv = 1.0f / l;
        const int r = qt * 128 + wq + g + 8 * e;
#pragma unroll
        for (int nt = 0; nt < 8; nt++) {
            __half2 h = __floats2half2_rn(accO[nt][2 * e] * inv,
                                          accO[nt][2 * e + 1] * inv);
            *reinterpret_cast<__half2*>(O + (long)r * 4096 + vOff + nt * 8 + tg * 2) = h;
        }
    }
}

// ---------------------------------------------------------------------------
extern "C" void kernel_launch(void* const* d_in, const int* in_sizes, int n_in,
                              void* d_out, int out_size) {
    const float* src        = (const float*)d_in[0];
    const float* pos        = (const float*)d_in[1];
    const float* in_proj_w  = (const float*)d_in[2];
    const float* alpha_in   = (const float*)d_in[3];
    const float* out_proj_w = (const float*)d_in[4];
    const float* alpha_out  = (const float*)d_in[5];
    const float* w1         = (const float*)d_in[6];
    const float* b1         = (const float*)d_in[7];
    const float* alpha1     = (const float*)d_in[8];
    const float* w2         = (const float*)d_in[9];
    const float* b2         = (const float*)d_in[10];
    const float* alpha2     = (const float*)d_in[11];
    const float* ln1_g      = (const float*)d_in[12];
    const float* ln1_b      = (const float*)d_in[13];
    const float* ln2_g      = (const float*)d_in[14];
    const float* ln2_b      = (const float*)d_in[15];
    float* out = (float*)d_out;

    __half *win_q, *wout_q, *w1_q, *w2_q, *src2h, *qkh, *qk2, *vh;
    __half *ctxh, *src2bh, *hbufh;
    float *res;
    cudaGetSymbolAddress((void**)&win_q,  g_win_q);
    cudaGetSymbolAddress((void**)&wout_q, g_wout_q);
    cudaGetSymbolAddress((void**)&w1_q,   g_w1_q);
    cudaGetSymbolAddress((void**)&w2_q,   g_w2_q);
    cudaGetSymbolAddress((void**)&src2h,  g_src2h);
    cudaGetSymbolAddress((void**)&qkh,    g_qkh);
    cudaGetSymbolAddress((void**)&qk2,    g_qk2);
    cudaGetSymbolAddress((void**)&vh,     g_vh);
    cudaGetSymbolAddress((void**)&ctxh,   g_ctxh);
    cudaGetSymbolAddress((void**)&res,    g_res);
    cudaGetSymbolAddress((void**)&src2bh, g_src2bh);
    cudaGetSymbolAddress((void**)&hbufh,  g_hbufh);

    cudaFuncSetAttribute(hgemm,
                         cudaFuncAttributeMaxDynamicSharedMemorySize, HG_SMEM);
    cudaFuncSetAttribute(flash_kernel,
                         cudaFuncAttributeMaxDynamicSharedMemorySize, FL_SMEM);

    // 1) quantize all weights (single launch)
    quant4_kernel<<<12288, 256>>>(
        (const float4*)in_proj_w, (const float4*)out_proj_w,
        (const float4*)w1, (const float4*)w2,
        alpha_in, alpha_out, alpha1, alpha2,
        (uint2*)win_q, (uint2*)wout_q, (uint2*)w1_q, (uint2*)w2_q);

    // 2) LN1 -> src2h (fp16), qkh = LN + pos (fp16)
    ln_kernel<true><<<MROWS, 256>>>(src, ln1_g, ln1_b, pos, src2h, qkh);

    // 3) fused Q+K projection: M=4096, N=2048, K=1024 (q cols scaled 1/8)
    hgemm<<<dim3(2048 / 128, MROWS / 128), 128, HG_SMEM>>>(
        qkh, win_q, nullptr, qk2, nullptr, nullptr, alpha_in,
        D_DIM, D_DIM, D_DIM, 2048, 0.125f, 1.0f, 1024, 0);

    //    V projection
    hgemm<<<dim3(D_DIM / 128, MROWS / 128), 128, HG_SMEM>>>(
        src2h, win_q + 2 * D_DIM * D_DIM, nullptr, vh, nullptr, nullptr,
        alpha_in, D_DIM, D_DIM, D_DIM, D_DIM, 1.0f, 1.0f, 1 << 30, 0);

    // 4) fused attention -> ctxh
    flash_kernel<<<dim3(S_DIM / 128, NBH), 256, FL_SMEM>>>(qk2, vh, ctxh);

    // 5) res = src + ctx @ Wout^T * alpha_out   (fp32 out)
    hgemm<<<dim3(D_DIM / 128, MROWS / 128), 128, HG_SMEM>>>(
        ctxh, wout_q, res, nullptr, nullptr, src, alpha_out,
        D_DIM, D_DIM, D_DIM, D_DIM, 1.0f, 1.0f, 1 << 30, 0);

    // 6) LN2 -> src2bh (fp16)
    ln_kernel<false><<<MROWS, 256>>>(res, ln2_g, ln2_b, nullptr, src2bh, nullptr);

    // 7) FFN1: h = relu(src2b @ W1^T * alpha1 + b1)  -> fp16
    hgemm<<<dim3(DFF_DIM / 128, MROWS / 128), 128, HG_SMEM>>>(
        src2bh, w1_q, nullptr, hbufh, b1, nullptr, alpha1,
        D_DIM, D_DIM, D_DIM, DFF_DIM, 1.0f, 1.0f, 1 << 30, 1);

    // 8) FFN2: out = res + h @ W2^T * alpha2 + b2  (fp32 out, K=4096)
    hgemm<<<dim3(D_DIM / 128, MROWS / 128), 128, HG_SMEM>>>(
        hbufh, w2_q, out, nullptr, b2, res, alpha2,
        DFF_DIM, DFF_DIM, DFF_DIM, D_DIM, 1.0f, 1.0f, 1 << 30, 0);
}

// round 14
// speedup vs baseline: 1.2526x; 1.0102x over previous
#include <cuda_runtime.h>
#include <cuda_fp16.h>
#include <cstdint>

// ---------------------------------------------------------------------------
// TransformerEncoderLayer  S=1024 B=4 D=1024 H=16 HD=64 DFF=4096, LSQ 4-bit
// Round 14: merged QKV projection (768-CTA single wave) + round-11 SYNCHRONOUS
// flash (the cp.async flash from r12/r13 is suspected of killing the
// container twice; reverted). GEMM core = round-11 (608.3us best).
// ---------------------------------------------------------------------------

#define S_DIM   1024
#define B_DIM   4
#define D_DIM   1024
#define H_DIM   16
#define HD_DIM  64
#define DFF_DIM 4096
#define MROWS   (S_DIM * B_DIM)        // 4096 token rows
#define NBH     (B_DIM * H_DIM)        // 64 batch*head

// ---------------- scratch (no cudaMalloc allowed) ----------------
__device__ __align__(16) __half g_win_q [3 * D_DIM * D_DIM];
__device__ __align__(16) __half g_wout_q[D_DIM * D_DIM];
__device__ __align__(16) __half g_w1_q  [DFF_DIM * D_DIM];
__device__ __align__(16) __half g_w2_q  [(size_t)D_DIM * DFF_DIM];
__device__ __align__(16) __half g_src2h [MROWS * D_DIM];
__device__ __align__(16) __half g_qkh   [MROWS * D_DIM];
__device__ __align__(16) __half g_qk2   [(size_t)MROWS * 2048];  // q|k fused
__device__ __align__(16) __half g_vh    [MROWS * D_DIM];
__device__ __align__(16) __half g_ctxh  [MROWS * D_DIM];
__device__ __align__(16) float  g_res   [MROWS * D_DIM];
__device__ __align__(16) __half g_src2bh[MROWS * D_DIM];
__device__ __align__(16) __half g_hbufh [(size_t)MROWS * DFF_DIM];

// ---------------- PTX helpers ----------------
__device__ __forceinline__ uint32_t smem_u32(const void* p) {
    return (uint32_t)__cvta_generic_to_shared(p);
}
__device__ __forceinline__ void cp16(void* smem, const void* g) {
    asm volatile("cp.async.cg.shared.global [%0], [%1], 16;"
                 :: "r"(smem_u32(smem)), "l"(g));
}
__device__ __forceinline__ void cp_commit() {
    asm volatile("cp.async.commit_group;");
}
template <int N>
__device__ __forceinline__ void cp_wait() {
    asm volatile("cp.async.wait_group %0;" :: "n"(N));
}
__device__ __forceinline__ void ldsm4(unsigned* r, const void* p) {
    unsigned a = smem_u32(p);
    asm volatile("ldmatrix.sync.aligned.m8n8.x4.shared.b16 {%0,%1,%2,%3}, [%4];"
                 : "=r"(r[0]), "=r"(r[1]), "=r"(r[2]), "=r"(r[3]) : "r"(a));
}
__device__ __forceinline__ void ldsm4t(unsigned* r, const void* p) {
    unsigned a = smem_u32(p);
    asm volatile("ldmatrix.sync.aligned.m8n8.x4.trans.shared.b16 {%0,%1,%2,%3}, [%4];"
                 : "=r"(r[0]), "=r"(r[1]), "=r"(r[2]), "=r"(r[3]) : "r"(a));
}
__device__ __forceinline__ void mma16816(float* d, const unsigned* a,
                                         unsigned b0, unsigned b1) {
    asm volatile(
        "mma.sync.aligned.m16n8k16.row.col.f32.f16.f16.f32 "
        "{%0,%1,%2,%3}, {%4,%5,%6,%7}, {%8,%9}, {%0,%1,%2,%3};\n"
        : "+f"(d[0]), "+f"(d[1]), "+f"(d[2]), "+f"(d[3])
        : "r"(a[0]), "r"(a[1]), "r"(a[2]), "r"(a[3]), "r"(b0), "r"(b1));
}
__device__ __forceinline__ unsigned packh2(float x, float y) {
    __half2 h = __floats2half2_rn(x, y);
    return *reinterpret_cast<unsigned*>(&h);
}

// ---------------- fused LSQ quant (all 4 weight mats, 1 launch) -------------
__global__ void __launch_bounds__(256)
quant4_kernel(const float4* __restrict__ w0, const float4* __restrict__ w1,
              const float4* __restrict__ w2, const float4* __restrict__ w3,
              const float* __restrict__ a0, const float* __restrict__ a1,
              const float* __restrict__ a2, const float* __restrict__ a3,
              uint2* __restrict__ o0, uint2* __restrict__ o1,
              uint2* __restrict__ o2, uint2* __restrict__ o3) {
    int j = blockIdx.x * blockDim.x + threadIdx.x;
    const float4* w; const float* a; uint2* o;
    if (j < 786432)                     { w = w0; a = a0; o = o0; }
    else if ((j -= 786432) < 262144)    { w = w1; a = a1; o = o1; }
    else if ((j -= 262144) < 1048576)   { w = w2; a = a2; o = o2; }
    else { j -= 1048576;                  w = w3; a = a3; o = o3; }
    const float ia = 1.0f / __ldg(a);
    const float4 v = w[j];
    const float q0 = rintf(fminf(fmaxf(v.x * ia, -8.0f), 7.0f));
    const float q1 = rintf(fminf(fmaxf(v.y * ia, -8.0f), 7.0f));
    const float q2 = rintf(fminf(fmaxf(v.z * ia, -8.0f), 7.0f));
    const float q3 = rintf(fminf(fmaxf(v.w * ia, -8.0f), 7.0f));
    o[j] = make_uint2(packh2(q0, q1), packh2(q2, q3));
}

// ---------------- LayerNorm (fp32 math, fp16 outputs, float4 I/O) -----------
template <bool WRITE_QK>
__global__ void __launch_bounds__(256)
ln_kernel(const float* __restrict__ x, const float* __restrict__ gam,
          const float* __restrict__ bet, const float* __restrict__ pos,
          __half* __restrict__ out, __half* __restrict__ qk) {
    __shared__ float red[256];
    const int row = blockIdx.x;
    const int t = threadIdx.x;
    const size_t rb = (size_t)row * D_DIM;

    const float4 xv = *reinterpret_cast<const float4*>(x + rb + 4 * t);
    float s = xv.x + xv.y + xv.z + xv.w;
    red[t] = s; __syncthreads();
    for (int off = 128; off > 0; off >>= 1) {
        if (t < off) red[t] += red[t + off];
        __syncthreads();
    }
    const float mean = red[0] * (1.0f / D_DIM);
    __syncthreads();

    const float d0 = xv.x - mean, d1 = xv.y - mean,
                d2 = xv.z - mean, d3 = xv.w - mean;
    red[t] = d0 * d0 + d1 * d1 + d2 * d2 + d3 * d3;
    __syncthreads();
    for (int off = 128; off > 0; off >>= 1) {
        if (t < off) red[t] += red[t + off];
        __syncthreads();
    }
    const float rstd = rsqrtf(red[0] * (1.0f / D_DIM) + 1e-5f);

    const float4 gv = *reinterpret_cast<const float4*>(gam + 4 * t);
    const float4 bv = *reinterpret_cast<const float4*>(bet + 4 * t);
    const float y0 = d0 * rstd * gv.x + bv.x;
    const float y1 = d1 * rstd * gv.y + bv.y;
    const float y2 = d2 * rstd * gv.z + bv.z;
    const float y3 = d3 * rstd * gv.w + bv.w;
    *reinterpret_cast<uint2*>(out + rb + 4 * t) =
        make_uint2(packh2(y0, y1), packh2(y2, y3));
    if (WRITE_QK) {
        const float4 pv = *reinterpret_cast<const float4*>(pos + rb + 4 * t);
        *reinterpret_cast<uint2*>(qk + rb + 4 * t) =
            make_uint2(packh2(y0 + pv.x, y1 + pv.y),
                       packh2(y2 + pv.z, y3 + pv.w));
    }
}

// ---------------- GEMM body (4 warps, 64x64, BK=64, 2-stage) ----------------
// C[m,n] = s(col)*alpha * sum_k A[m,k]*B[n,k]  (+bias, +resid fp32, relu)
// bnB: B-row base; bnC: output-column base (differ for merged QKV V-part).
#define HG_PITCH 72
#define HG_STAGE ((128 + 128) * HG_PITCH)        // halves per stage
#define HG_SMEM  (2 * HG_STAGE * 2)              // bytes = 73728
__device__ __forceinline__ void hgemm_body(
    const __half* __restrict__ A, const __half* __restrict__ Bm,
    float* __restrict__ C32, __half* __restrict__ C16,
    const float* __restrict__ bias, const float* __restrict__ resid,
    const float* __restrict__ alphaPtr,
    int K, int lda, int ldb, int ldc,
    float scaleLo, float scaleHi, int splitCol, int relu,
    int bm, int bnB, int bnC, __half* hsm) {
    const int tid = threadIdx.x;
    const int wid = tid >> 5;
    const int lane = tid & 31;
    const int wm = (wid & 1) * 64;
    const int wn = (wid >> 1) * 64;
    const int g = lane >> 2, tg = lane & 3;
    const int lrow = lane & 15;
    const int lcol = (lane >> 4) * 8;

    float acc[4][8][4];
#pragma unroll
    for (int i = 0; i < 4; i++)
#pragma unroll
        for (int j = 0; j < 8; j++)
#pragma unroll
            for (int e = 0; e < 4; e++) acc[i][j][e] = 0.f;

    const int TILES = K >> 6;

#define LOAD_TILE(kt, st)                                                     \
    {                                                                         \
        const int k0 = (kt) << 6;                                             \
        __half* sA = hsm + (st) * HG_STAGE;                                   \
        __half* sB = sA + 128 * HG_PITCH;                                     \
        _Pragma("unroll")                                                     \
        for (int t = 0; t < 8; t++) {                                         \
            const int i = tid + t * 128;                                      \
            const int r = i >> 3, c = (i & 7) * 8;                            \
            cp16(&sA[r * HG_PITCH + c], A + (long)(bm + r) * lda + k0 + c);   \
            cp16(&sB[r * HG_PITCH + c], Bm + (long)(bnB + r) * ldb + k0 + c); \
        }                                                                     \
    }

#define LOAD_FRAG(sA, sB, ks, pb)                                             \
    {                                                                         \
        _Pragma("unroll")                                                     \
        for (int mt = 0; mt < 4; mt++)                                        \
            ldsm4(af[pb][mt],                                                 \
                  &sA[(wm + mt * 16 + lrow) * HG_PITCH + (ks) + lcol]);       \
        _Pragma("unroll")                                                     \
        for (int i = 0; i < 4; i++) {                                         \
            unsigned b4[4];                                                   \
            ldsm4(b4, &sB[(wn + i * 16 + lrow) * HG_PITCH + (ks) + lcol]);    \
            bf[pb][2 * i][0] = b4[0]; bf[pb][2 * i][1] = b4[2];               \
            bf[pb][2 * i + 1][0] = b4[1]; bf[pb][2 * i + 1][1] = b4[3];       \
        }                                                                     \
    }

    LOAD_TILE(0, 0);
    cp_commit();

    unsigned af[2][4][4];
    unsigned bf[2][8][2];

    for (int kt = 0; kt < TILES; ++kt) {
        if (kt + 1 < TILES) LOAD_TILE(kt + 1, (kt + 1) & 1);
        cp_commit();
        cp_wait<1>();
        __syncthreads();

        const __half* sA = hsm + (kt & 1) * HG_STAGE;
        const __half* sB = sA + 128 * HG_PITCH;

        LOAD_FRAG(sA, sB, 0, 0);
#pragma unroll
        for (int s = 0; s < 4; ++s) {
            const int cur = s & 1;
            if (s < 3) LOAD_FRAG(sA, sB, (s + 1) * 16, cur ^ 1);
#pragma unroll
            for (int mt = 0; mt < 4; mt++)
#pragma unroll
                for (int nt = 0; nt < 8; nt++)
                    mma16816(acc[mt][nt], af[cur][mt],
                             bf[cur][nt][0], bf[cur][nt][1]);
        }
        __syncthreads();
    }
#undef LOAD_FRAG
#undef LOAD_TILE

    const float al = alphaPtr ? __ldg(alphaPtr) : 1.0f;
#pragma unroll
    for (int mt = 0; mt < 4; mt++) {
#pragma unroll
        for (int nt = 0; nt < 8; nt++) {
            const int row0 = bm + wm + mt * 16 + g;
            const int col0 = bnC + wn + nt * 8 + tg * 2;
            const float sc = (col0 < splitCol ? scaleLo : scaleHi) * al;
            float bx = 0.f, by = 0.f;
            if (bias) {
                const float2 bb = *reinterpret_cast<const float2*>(&bias[col0]);
                bx = bb.x; by = bb.y;
            }
#pragma unroll
            for (int h = 0; h < 2; ++h) {
                const int row = row0 + h * 8;
                float v0 = acc[mt][nt][2 * h] * sc + bx;
                float v1 = acc[mt][nt][2 * h + 1] * sc + by;
                if (resid) {
                    const float2 rr = *reinterpret_cast<const float2*>(
                        &resid[(long)row * ldc + col0]);
                    v0 += rr.x; v1 += rr.y;
                }
                if (relu) { v0 = fmaxf(v0, 0.f); v1 = fmaxf(v1, 0.f); }
                if (C32)
                    *reinterpret_cast<float2*>(&C32[(long)row * ldc + col0]) =
                        make_float2(v0, v1);
                if (C16)
                    *reinterpret_cast<__half2*>(&C16[(long)row * ldc + col0]) =
                        __floats2half2_rn(v0, v1);
            }
        }
    }
}

__global__ void __launch_bounds__(128, 2)
hgemm(const __half* __restrict__ A, const __half* __restrict__ Bm,
      float* __restrict__ C32, __half* __restrict__ C16,
      const float* __restrict__ bias, const float* __restrict__ resid,
      const float* __restrict__ alphaPtr,
      int K, int lda, int ldb, int ldc,
      float scaleLo, float scaleHi, int splitCol, int relu) {
    extern __shared__ __half hsm[];
    hgemm_body(A, Bm, C32, C16, bias, resid, alphaPtr, K, lda, ldb, ldc,
               scaleLo, scaleHi, splitCol, relu,
               blockIdx.y * 128, blockIdx.x * 128, blockIdx.x * 128, hsm);
}

// merged QKV projection: grid (24, 32). bn<2048 -> QK part (A=qkh, C=qk2,
// ldc=2048, q cols scaled 1/8); else V part (A=src2h, C=vh, ldc=1024).
__global__ void __launch_bounds__(128, 2)
qkv_kernel(const __half* __restrict__ qkh, const __half* __restrict__ src2h,
           const __half* __restrict__ winq, __half* __restrict__ qk2,
           __half* __restrict__ vh, const float* __restrict__ alphaPtr) {
    extern __shared__ __half hsm[];
    const int bnT = blockIdx.x * 128;
    const int bm = blockIdx.y * 128;
    if (bnT < 2048)
        hgemm_body(qkh, winq, nullptr, qk2, nullptr, nullptr, alphaPtr,
                   D_DIM, D_DIM, D_DIM, 2048, 0.125f, 1.0f, 1024, 0,
                   bm, bnT, bnT, hsm);
    else
        hgemm_body(src2h, winq, nullptr, vh, nullptr, nullptr, alphaPtr,
                   D_DIM, D_DIM, D_DIM, 1024, 1.0f, 1.0f, 1 << 30, 0,
                   bm, bnT, bnT - 2048, hsm);
}

// ---------------- fused flash attention (round-11 synchronous version) ------
// grid (8, 64): blockIdx.x = q-tile (128 rows), blockIdx.y = z = b*16+h.
// 256 threads = 8 warps; warp handles 16 q rows. Q pre-scaled by 1/8.
// Q/K in qk2: elem (s,b,h,d) = s*8192 + b*2048 + h*64 + d (K at +1024).
// V/O: s*4096 + b*1024 + h*64 + d.
#define FL_SMEM (3 * 128 * 72 * 2)
__global__ void __launch_bounds__(256)
flash_kernel(const __half* __restrict__ QK2, const __half* __restrict__ Vg,
             __half* __restrict__ O) {
    extern __shared__ __half fsm[];
    __half (*Qs)[72] = reinterpret_cast<__half(*)[72]>(fsm);
    __half (*Ks)[72] = reinterpret_cast<__half(*)[72]>(fsm + 128 * 72);
    __half (*Vs)[72] = reinterpret_cast<__half(*)[72]>(fsm + 2 * 128 * 72);

    const int z = blockIdx.y;
    const int qt = blockIdx.x;
    const int tid = threadIdx.x;
    const int wid = tid >> 5, lane = tid & 31;
    const int g = lane >> 2, tg = lane & 3;
    const int lrow = lane & 15, lcol = (lane >> 4) * 8;
    const long qOff = (long)(z >> 4) * 2048 + (z & 15) * 64;
    const long vOff = (long)z * 64;
    const int wq = wid * 16;

    for (int i = tid; i < 128 * 8; i += 256) {
        const int r = i >> 3, c = (i & 7) * 8;
        *reinterpret_cast<int4*>(&Qs[r][c]) =
            *reinterpret_cast<const int4*>(QK2 + qOff + (long)(qt * 128 + r) * 8192 + c);
    }

    float accO[8][4];
#pragma unroll
    for (int i = 0; i < 8; i++)
#pragma unroll
        for (int e = 0; e < 4; e++) accO[i][e] = 0.f;
    float mrow[2] = {-1e30f, -1e30f};
    float lrow_[2] = {0.f, 0.f};

    for (int t = 0; t < 8; ++t) {
        __syncthreads();
        for (int i = tid; i < 128 * 8; i += 256) {
            const int r = i >> 3, c = (i & 7) * 8;
            *reinterpret_cast<int4*>(&Ks[r][c]) =
                *reinterpret_cast<const int4*>(QK2 + 1024 + qOff +
                                               (long)(t * 128 + r) * 8192 + c);
            *reinterpret_cast<int4*>(&Vs[r][c]) =
                *reinterpret_cast<const int4*>(Vg + vOff +
                                               (long)(t * 128 + r) * 4096 + c);
        }
        __syncthreads();

        float accS[16][4];
#pragma unroll
        for (int i = 0; i < 16; i++)
#pragma unroll
            for (int e = 0; e < 4; e++) accS[i][e] = 0.f;

#pragma unroll
        for (int kc = 0; kc < 4; ++kc) {
            unsigned a[4];
            ldsm4(a, &Qs[wq + lrow][kc * 16 + lcol]);
#pragma unroll
            for (int i = 0; i < 8; ++i) {
                unsigned b4[4];
                ldsm4(b4, &Ks[i * 16 + lrow][kc * 16 + lcol]);
                mma16816(accS[2 * i], a, b4[0], b4[2]);
                mma16816(accS[2 * i + 1], a, b4[1], b4[3]);
            }
        }

#pragma unroll
        for (int e = 0; e < 2; ++e) {
            float rmax = -1e30f;
#pragma unroll
            for (int nt = 0; nt < 16; nt++)
                rmax = fmaxf(rmax, fmaxf(accS[nt][2 * e], accS[nt][2 * e + 1]));
            rmax = fmaxf(rmax, __shfl_xor_sync(0xffffffffu, rmax, 1));
            rmax = fmaxf(rmax, __shfl_xor_sync(0xffffffffu, rmax, 2));
            const float mnew = fmaxf(mrow[e], rmax);
            const float corr = __expf(mrow[e] - mnew);
            mrow[e] = mnew;
            lrow_[e] *= corr;
#pragma unroll
            for (int nt = 0; nt < 8; nt++) {
                accO[nt][2 * e] *= corr;
                accO[nt][2 * e + 1] *= corr;
            }
            float sum = 0.f;
#pragma unroll
            for (int nt = 0; nt < 16; nt++) {
                const float p0 = __expf(accS[nt][2 * e] - mnew);
                const float p1 = __expf(accS[nt][2 * e + 1] - mnew);
                accS[nt][2 * e] = p0; accS[nt][2 * e + 1] = p1;
                sum += p0 + p1;
            }
            lrow_[e] += sum;
        }

#pragma unroll
        for (int j = 0; j < 8; ++j) {
            unsigned aP[4];
            aP[0] = packh2(accS[2 * j][0], accS[2 * j][1]);
            aP[1] = packh2(accS[2 * j][2], accS[2 * j][3]);
            aP[2] = packh2(accS[2 * j + 1][0], accS[2 * j + 1][1]);
            aP[3] = packh2(accS[2 * j + 1][2], accS[2 * j + 1][3]);
#pragma unroll
            for (int i = 0; i < 4; ++i) {
                unsigned b4[4];
                ldsm4t(b4, &Vs[j * 16 + (lane & 7) + ((lane >> 3) & 1) * 8]
                           [i * 16 + (lane >> 4) * 8]);
                mma16816(accO[2 * i], aP, b4[0], b4[1]);
                mma16816(accO[2 * i + 1], aP, b4[2], b4[3]);
            }
        }
    }

#pragma unroll
    for (int e = 0; e < 2; ++e) {
        float l = lrow_[e];
        l += __shfl_xor_sync(0xffffffffu, l, 1);
        l += __shfl_xor_sync(0xffffffffu, l, 2);
        const float inv = 1.0f / l;
        const int r = qt * 128 + wq + g + 8 * e;
#pragma unroll
        for (int nt = 0; nt < 8; nt++) {
            __half2 h = __floats2half2_rn(accO[nt][2 * e] * inv,
                                          accO[nt][2 * e + 1] * inv);
            *reinterpret_cast<__half2*>(O + (long)r * 4096 + vOff + nt * 8 + tg * 2) = h;
        }
    }
}

// ---------------------------------------------------------------------------
extern "C" void kernel_launch(void* const* d_in, const int* in_sizes, int n_in,
                              void* d_out, int out_size) {
    const float* src        = (const float*)d_in[0];
    const float* pos        = (const float*)d_in[1];
    const float* in_proj_w  = (const float*)d_in[2];
    const float* alpha_in   = (const float*)d_in[3];
    const float* out_proj_w = (const float*)d_in[4];
    const float* alpha_out  = (const float*)d_in[5];
    const float* w1         = (const float*)d_in[6];
    const float* b1         = (const float*)d_in[7];
    const float* alpha1     = (const float*)d_in[8];
    const float* w2         = (const float*)d_in[9];
    const float* b2         = (const float*)d_in[10];
    const float* alpha2     = (const float*)d_in[11];
    const float* ln1_g      = (const float*)d_in[12];
    const float* ln1_b      = (const float*)d_in[13];
    const float* ln2_g      = (const float*)d_in[14];
    const float* ln2_b      = (const float*)d_in[15];
    float* out = (float*)d_out;

    __half *win_q, *wout_q, *w1_q, *w2_q, *src2h, *qkh, *qk2, *vh;
    __half *ctxh, *src2bh, *hbufh;
    float *res;
    cudaGetSymbolAddress((void**)&win_q,  g_win_q);
    cudaGetSymbolAddress((void**)&wout_q, g_wout_q);
    cudaGetSymbolAddress((void**)&w1_q,   g_w1_q);
    cudaGetSymbolAddress((void**)&w2_q,   g_w2_q);
    cudaGetSymbolAddress((void**)&src2h,  g_src2h);
    cudaGetSymbolAddress((void**)&qkh,    g_qkh);
    cudaGetSymbolAddress((void**)&qk2,    g_qk2);
    cudaGetSymbolAddress((void**)&vh,     g_vh);
    cudaGetSymbolAddress((void**)&ctxh,   g_ctxh);
    cudaGetSymbolAddress((void**)&res,    g_res);
    cudaGetSymbolAddress((void**)&src2bh, g_src2bh);
    cudaGetSymbolAddress((void**)&hbufh,  g_hbufh);

    cudaFuncSetAttribute(hgemm,
                         cudaFuncAttributeMaxDynamicSharedMemorySize, HG_SMEM);
    cudaFuncSetAttribute(qkv_kernel,
                         cudaFuncAttributeMaxDynamicSharedMemorySize, HG_SMEM);
    cudaFuncSetAttribute(flash_kernel,
                         cudaFuncAttributeMaxDynamicSharedMemorySize, FL_SMEM);

    // 1) quantize all weights (single launch)
    quant4_kernel<<<12288, 256>>>(
        (const float4*)in_proj_w, (const float4*)out_proj_w,
        (const float4*)w1, (const float4*)w2,
        alpha_in, alpha_out, alpha1, alpha2,
        (uint2*)win_q, (uint2*)wout_q, (uint2*)w1_q, (uint2*)w2_q);

    // 2) LN1 -> src2h (fp16), qkh = LN + pos (fp16)
    ln_kernel<true><<<MROWS, 256>>>(src, ln1_g, ln1_b, pos, src2h, qkh);

    // 3) merged QKV projection (768 CTAs)
    qkv_kernel<<<dim3(3072 / 128, MROWS / 128), 128, HG_SMEM>>>(
        qkh, src2h, win_q, qk2, vh, alpha_in);

    // 4) fused attention -> ctxh
    flash_kernel<<<dim3(S_DIM / 128, NBH), 256, FL_SMEM>>>(qk2, vh, ctxh);

    // 5) res = src + ctx @ Wout^T * alpha_out   (fp32 out)
    hgemm<<<dim3(D_DIM / 128, MROWS / 128), 128, HG_SMEM>>>(
        ctxh, wout_q, res, nullptr, nullptr, src, alpha_out,
        D_DIM, D_DIM, D_DIM, D_DIM, 1.0f, 1.0f, 1 << 30, 0);

    // 6) LN2 -> src2bh (fp16)
    ln_kernel<false><<<MROWS, 256>>>(res, ln2_g, ln2_b, nullptr, src2bh, nullptr);

    // 7) FFN1: h = relu(src2b @ W1^T * alpha1 + b1)  -> fp16
    hgemm<<<dim3(DFF_DIM / 128, MROWS / 128), 128, HG_SMEM>>>(
        src2bh, w1_q, nullptr, hbufh, b1, nullptr, alpha1,
        D_DIM, D_DIM, D_DIM, DFF_DIM, 1.0f, 1.0f, 1 << 30, 1);

    // 8) FFN2: out = res + h @ W2^T * alpha2 + b2  (fp32 out, K=4096)
    hgemm<<<dim3(D_DIM / 128, MROWS / 128), 128, HG_SMEM>>>(
        hbufh, w2_q, out, nullptr, b2, res, alpha2,
        DFF_DIM, DFF_DIM, DFF_DIM, D_DIM, 1.0f, 1.0f, 1 << 30, 0);
}

// round 15
// speedup vs baseline: 1.3676x; 1.0919x over previous
#include <cuda_runtime.h>
#include <cuda_fp16.h>
#include <cstdint>

// ---------------------------------------------------------------------------
// TransformerEncoderLayer  S=1024 B=4 D=1024 H=16 HD=64 DFF=4096, LSQ 4-bit
// Round 15: flash_kernel __launch_bounds__(256,2) — regs 134 -> 128 so 2
// CTAs/SM co-reside (was 1 CTA/SM, occ 12.4%, 161.9us = 27% of runtime).
// Everything else identical to round 14 (602.1us best).
// ---------------------------------------------------------------------------

#define S_DIM   1024
#define B_DIM   4
#define D_DIM   1024
#define H_DIM   16
#define HD_DIM  64
#define DFF_DIM 4096
#define MROWS   (S_DIM * B_DIM)        // 4096 token rows
#define NBH     (B_DIM * H_DIM)        // 64 batch*head

// ---------------- scratch (no cudaMalloc allowed) ----------------
__device__ __align__(16) __half g_win_q [3 * D_DIM * D_DIM];
__device__ __align__(16) __half g_wout_q[D_DIM * D_DIM];
__device__ __align__(16) __half g_w1_q  [DFF_DIM * D_DIM];
__device__ __align__(16) __half g_w2_q  [(size_t)D_DIM * DFF_DIM];
__device__ __align__(16) __half g_src2h [MROWS * D_DIM];
__device__ __align__(16) __half g_qkh   [MROWS * D_DIM];
__device__ __align__(16) __half g_qk2   [(size_t)MROWS * 2048];  // q|k fused
__device__ __align__(16) __half g_vh    [MROWS * D_DIM];
__device__ __align__(16) __half g_ctxh  [MROWS * D_DIM];
__device__ __align__(16) float  g_res   [MROWS * D_DIM];
__device__ __align__(16) __half g_src2bh[MROWS * D_DIM];
__device__ __align__(16) __half g_hbufh [(size_t)MROWS * DFF_DIM];

// ---------------- PTX helpers ----------------
__device__ __forceinline__ uint32_t smem_u32(const void* p) {
    return (uint32_t)__cvta_generic_to_shared(p);
}
__device__ __forceinline__ void cp16(void* smem, const void* g) {
    asm volatile("cp.async.cg.shared.global [%0], [%1], 16;"
                 :: "r"(smem_u32(smem)), "l"(g));
}
__device__ __forceinline__ void cp_commit() {
    asm volatile("cp.async.commit_group;");
}
template <int N>
__device__ __forceinline__ void cp_wait() {
    asm volatile("cp.async.wait_group %0;" :: "n"(N));
}
__device__ __forceinline__ void ldsm4(unsigned* r, const void* p) {
    unsigned a = smem_u32(p);
    asm volatile("ldmatrix.sync.aligned.m8n8.x4.shared.b16 {%0,%1,%2,%3}, [%4];"
                 : "=r"(r[0]), "=r"(r[1]), "=r"(r[2]), "=r"(r[3]) : "r"(a));
}
__device__ __forceinline__ void ldsm4t(unsigned* r, const void* p) {
    unsigned a = smem_u32(p);
    asm volatile("ldmatrix.sync.aligned.m8n8.x4.trans.shared.b16 {%0,%1,%2,%3}, [%4];"
                 : "=r"(r[0]), "=r"(r[1]), "=r"(r[2]), "=r"(r[3]) : "r"(a));
}
__device__ __forceinline__ void mma16816(float* d, const unsigned* a,
                                         unsigned b0, unsigned b1) {
    asm volatile(
        "mma.sync.aligned.m16n8k16.row.col.f32.f16.f16.f32 "
        "{%0,%1,%2,%3}, {%4,%5,%6,%7}, {%8,%9}, {%0,%1,%2,%3};\n"
        : "+f"(d[0]), "+f"(d[1]), "+f"(d[2]), "+f"(d[3])
        : "r"(a[0]), "r"(a[1]), "r"(a[2]), "r"(a[3]), "r"(b0), "r"(b1));
}
__device__ __forceinline__ unsigned packh2(float x, float y) {
    __half2 h = __floats2half2_rn(x, y);
    return *reinterpret_cast<unsigned*>(&h);
}

// ---------------- fused LSQ quant (all 4 weight mats, 1 launch) -------------
__global__ void __launch_bounds__(256)
quant4_kernel(const float4* __restrict__ w0, const float4* __restrict__ w1,
              const float4* __restrict__ w2, const float4* __restrict__ w3,
              const float* __restrict__ a0, const float* __restrict__ a1,
              const float* __restrict__ a2, const float* __restrict__ a3,
              uint2* __restrict__ o0, uint2* __restrict__ o1,
              uint2* __restrict__ o2, uint2* __restrict__ o3) {
    int j = blockIdx.x * blockDim.x + threadIdx.x;
    const float4* w; const float* a; uint2* o;
    if (j < 786432)                     { w = w0; a = a0; o = o0; }
    else if ((j -= 786432) < 262144)    { w = w1; a = a1; o = o1; }
    else if ((j -= 262144) < 1048576)   { w = w2; a = a2; o = o2; }
    else { j -= 1048576;                  w = w3; a = a3; o = o3; }
    const float ia = 1.0f / __ldg(a);
    const float4 v = w[j];
    const float q0 = rintf(fminf(fmaxf(v.x * ia, -8.0f), 7.0f));
    const float q1 = rintf(fminf(fmaxf(v.y * ia, -8.0f), 7.0f));
    const float q2 = rintf(fminf(fmaxf(v.z * ia, -8.0f), 7.0f));
    const float q3 = rintf(fminf(fmaxf(v.w * ia, -8.0f), 7.0f));
    o[j] = make_uint2(packh2(q0, q1), packh2(q2, q3));
}

// ---------------- LayerNorm (fp32 math, fp16 outputs, float4 I/O) -----------
template <bool WRITE_QK>
__global__ void __launch_bounds__(256)
ln_kernel(const float* __restrict__ x, const float* __restrict__ gam,
          const float* __restrict__ bet, const float* __restrict__ pos,
          __half* __restrict__ out, __half* __restrict__ qk) {
    __shared__ float red[256];
    const int row = blockIdx.x;
    const int t = threadIdx.x;
    const size_t rb = (size_t)row * D_DIM;

    const float4 xv = *reinterpret_cast<const float4*>(x + rb + 4 * t);
    float s = xv.x + xv.y + xv.z + xv.w;
    red[t] = s; __syncthreads();
    for (int off = 128; off > 0; off >>= 1) {
        if (t < off) red[t] += red[t + off];
        __syncthreads();
    }
    const float mean = red[0] * (1.0f / D_DIM);
    __syncthreads();

    const float d0 = xv.x - mean, d1 = xv.y - mean,
                d2 = xv.z - mean, d3 = xv.w - mean;
    red[t] = d0 * d0 + d1 * d1 + d2 * d2 + d3 * d3;
    __syncthreads();
    for (int off = 128; off > 0; off >>= 1) {
        if (t < off) red[t] += red[t + off];
        __syncthreads();
    }
    const float rstd = rsqrtf(red[0] * (1.0f / D_DIM) + 1e-5f);

    const float4 gv = *reinterpret_cast<const float4*>(gam + 4 * t);
    const float4 bv = *reinterpret_cast<const float4*>(bet + 4 * t);
    const float y0 = d0 * rstd * gv.x + bv.x;
    const float y1 = d1 * rstd * gv.y + bv.y;
    const float y2 = d2 * rstd * gv.z + bv.z;
    const float y3 = d3 * rstd * gv.w + bv.w;
    *reinterpret_cast<uint2*>(out + rb + 4 * t) =
        make_uint2(packh2(y0, y1), packh2(y2, y3));
    if (WRITE_QK) {
        const float4 pv = *reinterpret_cast<const float4*>(pos + rb + 4 * t);
        *reinterpret_cast<uint2*>(qk + rb + 4 * t) =
            make_uint2(packh2(y0 + pv.x, y1 + pv.y),
                       packh2(y2 + pv.z, y3 + pv.w));
    }
}

// ---------------- GEMM body (4 warps, 64x64, BK=64, 2-stage) ----------------
// C[m,n] = s(col)*alpha * sum_k A[m,k]*B[n,k]  (+bias, +resid fp32, relu)
// bnB: B-row base; bnC: output-column base (differ for merged QKV V-part).
#define HG_PITCH 72
#define HG_STAGE ((128 + 128) * HG_PITCH)        // halves per stage
#define HG_SMEM  (2 * HG_STAGE * 2)              // bytes = 73728
__device__ __forceinline__ void hgemm_body(
    const __half* __restrict__ A, const __half* __restrict__ Bm,
    float* __restrict__ C32, __half* __restrict__ C16,
    const float* __restrict__ bias, const float* __restrict__ resid,
    const float* __restrict__ alphaPtr,
    int K, int lda, int ldb, int ldc,
    float scaleLo, float scaleHi, int splitCol, int relu,
    int bm, int bnB, int bnC, __half* hsm) {
    const int tid = threadIdx.x;
    const int wid = tid >> 5;
    const int lane = tid & 31;
    const int wm = (wid & 1) * 64;
    const int wn = (wid >> 1) * 64;
    const int g = lane >> 2, tg = lane & 3;
    const int lrow = lane & 15;
    const int lcol = (lane >> 4) * 8;

    float acc[4][8][4];
#pragma unroll
    for (int i = 0; i < 4; i++)
#pragma unroll
        for (int j = 0; j < 8; j++)
#pragma unroll
            for (int e = 0; e < 4; e++) acc[i][j][e] = 0.f;

    const int TILES = K >> 6;

#define LOAD_TILE(kt, st)                                                     \
    {                                                                         \
        const int k0 = (kt) << 6;                                             \
        __half* sA = hsm + (st) * HG_STAGE;                                   \
        __half* sB = sA + 128 * HG_PITCH;                                     \
        _Pragma("unroll")                                                     \
        for (int t = 0; t < 8; t++) {                                         \
            const int i = tid + t * 128;                                      \
            const int r = i >> 3, c = (i & 7) * 8;                            \
            cp16(&sA[r * HG_PITCH + c], A + (long)(bm + r) * lda + k0 + c);   \
            cp16(&sB[r * HG_PITCH + c], Bm + (long)(bnB + r) * ldb + k0 + c); \
        }                                                                     \
    }

#define LOAD_FRAG(sA, sB, ks, pb)                                             \
    {                                                                         \
        _Pragma("unroll")                                                     \
        for (int mt = 0; mt < 4; mt++)                                        \
            ldsm4(af[pb][mt],                                                 \
                  &sA[(wm + mt * 16 + lrow) * HG_PITCH + (ks) + lcol]);       \
        _Pragma("unroll")                                                     \
        for (int i = 0; i < 4; i++) {                                         \
            unsigned b4[4];                                                   \
            ldsm4(b4, &sB[(wn + i * 16 + lrow) * HG_PITCH + (ks) + lcol]);    \
            bf[pb][2 * i][0] = b4[0]; bf[pb][2 * i][1] = b4[2];               \
            bf[pb][2 * i + 1][0] = b4[1]; bf[pb][2 * i + 1][1] = b4[3];       \
        }                                                                     \
    }

    LOAD_TILE(0, 0);
    cp_commit();

    unsigned af[2][4][4];
    unsigned bf[2][8][2];

    for (int kt = 0; kt < TILES; ++kt) {
        if (kt + 1 < TILES) LOAD_TILE(kt + 1, (kt + 1) & 1);
        cp_commit();
        cp_wait<1>();
        __syncthreads();

        const __half* sA = hsm + (kt & 1) * HG_STAGE;
        const __half* sB = sA + 128 * HG_PITCH;

        LOAD_FRAG(sA, sB, 0, 0);
#pragma unroll
        for (int s = 0; s < 4; ++s) {
            const int cur = s & 1;
            if (s < 3) LOAD_FRAG(sA, sB, (s + 1) * 16, cur ^ 1);
#pragma unroll
            for (int mt = 0; mt < 4; mt++)
#pragma unroll
                for (int nt = 0; nt < 8; nt++)
                    mma16816(acc[mt][nt], af[cur][mt],
                             bf[cur][nt][0], bf[cur][nt][1]);
        }
        __syncthreads();
    }
#undef LOAD_FRAG
#undef LOAD_TILE

    const float al = alphaPtr ? __ldg(alphaPtr) : 1.0f;
#pragma unroll
    for (int mt = 0; mt < 4; mt++) {
#pragma unroll
        for (int nt = 0; nt < 8; nt++) {
            const int row0 = bm + wm + mt * 16 + g;
            const int col0 = bnC + wn + nt * 8 + tg * 2;
            const float sc = (col0 < splitCol ? scaleLo : scaleHi) * al;
            float bx = 0.f, by = 0.f;
            if (bias) {
                const float2 bb = *reinterpret_cast<const float2*>(&bias[col0]);
                bx = bb.x; by = bb.y;
            }
#pragma unroll
            for (int h = 0; h < 2; ++h) {
                const int row = row0 + h * 8;
                float v0 = acc[mt][nt][2 * h] * sc + bx;
                float v1 = acc[mt][nt][2 * h + 1] * sc + by;
                if (resid) {
                    const float2 rr = *reinterpret_cast<const float2*>(
                        &resid[(long)row * ldc + col0]);
                    v0 += rr.x; v1 += rr.y;
                }
                if (relu) { v0 = fmaxf(v0, 0.f); v1 = fmaxf(v1, 0.f); }
                if (C32)
                    *reinterpret_cast<float2*>(&C32[(long)row * ldc + col0]) =
                        make_float2(v0, v1);
                if (C16)
                    *reinterpret_cast<__half2*>(&C16[(long)row * ldc + col0]) =
                        __floats2half2_rn(v0, v1);
            }
        }
    }
}

__global__ void __launch_bounds__(128, 2)
hgemm(const __half* __restrict__ A, const __half* __restrict__ Bm,
      float* __restrict__ C32, __half* __restrict__ C16,
      const float* __restrict__ bias, const float* __restrict__ resid,
      const float* __restrict__ alphaPtr,
      int K, int lda, int ldb, int ldc,
      float scaleLo, float scaleHi, int splitCol, int relu) {
    extern __shared__ __half hsm[];
    hgemm_body(A, Bm, C32, C16, bias, resid, alphaPtr, K, lda, ldb, ldc,
               scaleLo, scaleHi, splitCol, relu,
               blockIdx.y * 128, blockIdx.x * 128, blockIdx.x * 128, hsm);
}

// merged QKV projection: grid (24, 32). bn<2048 -> QK part (A=qkh, C=qk2,
// ldc=2048, q cols scaled 1/8); else V part (A=src2h, C=vh, ldc=1024).
__global__ void __launch_bounds__(128, 2)
qkv_kernel(const __half* __restrict__ qkh, const __half* __restrict__ src2h,
           const __half* __restrict__ winq, __half* __restrict__ qk2,
           __half* __restrict__ vh, const float* __restrict__ alphaPtr) {
    extern __shared__ __half hsm[];
    const int bnT = blockIdx.x * 128;
    const int bm = blockIdx.y * 128;
    if (bnT < 2048)
        hgemm_body(qkh, winq, nullptr, qk2, nullptr, nullptr, alphaPtr,
                   D_DIM, D_DIM, D_DIM, 2048, 0.125f, 1.0f, 1024, 0,
                   bm, bnT, bnT, hsm);
    else
        hgemm_body(src2h, winq, nullptr, vh, nullptr, nullptr, alphaPtr,
                   D_DIM, D_DIM, D_DIM, 1024, 1.0f, 1.0f, 1 << 30, 0,
                   bm, bnT, bnT - 2048, hsm);
}

// ---------------- fused flash attention (synchronous, 2 CTAs/SM) ------------
// grid (8, 64): blockIdx.x = q-tile (128 rows), blockIdx.y = z = b*16+h.
// 256 threads = 8 warps; warp handles 16 q rows. Q pre-scaled by 1/8.
// Q/K in qk2: elem (s,b,h,d) = s*8192 + b*2048 + h*64 + d (K at +1024).
// V/O: s*4096 + b*1024 + h*64 + d.
#define FL_SMEM (3 * 128 * 72 * 2)
__global__ void __launch_bounds__(256, 2)
flash_kernel(const __half* __restrict__ QK2, const __half* __restrict__ Vg,
             __half* __restrict__ O) {
    extern __shared__ __half fsm[];
    __half (*Qs)[72] = reinterpret_cast<__half(*)[72]>(fsm);
    __half (*Ks)[72] = reinterpret_cast<__half(*)[72]>(fsm + 128 * 72);
    __half (*Vs)[72] = reinterpret_cast<__half(*)[72]>(fsm + 2 * 128 * 72);

    const int z = blockIdx.y;
    const int qt = blockIdx.x;
    const int tid = threadIdx.x;
    const int wid = tid >> 5, lane = tid & 31;
    const int g = lane >> 2, tg = lane & 3;
    const int lrow = lane & 15, lcol = (lane >> 4) * 8;
    const long qOff = (long)(z >> 4) * 2048 + (z & 15) * 64;
    const long vOff = (long)z * 64;
    const int wq = wid * 16;

    for (int i = tid; i < 128 * 8; i += 256) {
        const int r = i >> 3, c = (i & 7) * 8;
        *reinterpret_cast<int4*>(&Qs[r][c]) =
            *reinterpret_cast<const int4*>(QK2 + qOff + (long)(qt * 128 + r) * 8192 + c);
    }

    float accO[8][4];
#pragma unroll
    for (int i = 0; i < 8; i++)
#pragma unroll
        for (int e = 0; e < 4; e++) accO[i][e] = 0.f;
    float mrow[2] = {-1e30f, -1e30f};
    float lrow_[2] = {0.f, 0.f};

    for (int t = 0; t < 8; ++t) {
        __syncthreads();
        for (int i = tid; i < 128 * 8; i += 256) {
            const int r = i >> 3, c = (i & 7) * 8;
            *reinterpret_cast<int4*>(&Ks[r][c]) =
                *reinterpret_cast<const int4*>(QK2 + 1024 + qOff +
                                               (long)(t * 128 + r) * 8192 + c);
            *reinterpret_cast<int4*>(&Vs[r][c]) =
                *reinterpret_cast<const int4*>(Vg + vOff +
                                               (long)(t * 128 + r) * 4096 + c);
        }
        __syncthreads();

        float accS[16][4];
#pragma unroll
        for (int i = 0; i < 16; i++)
#pragma unroll
            for (int e = 0; e < 4; e++) accS[i][e] = 0.f;

#pragma unroll
        for (int kc = 0; kc < 4; ++kc) {
            unsigned a[4];
            ldsm4(a, &Qs[wq + lrow][kc * 16 + lcol]);
#pragma unroll
            for (int i = 0; i < 8; ++i) {
                unsigned b4[4];
                ldsm4(b4, &Ks[i * 16 + lrow][kc * 16 + lcol]);
                mma16816(accS[2 * i], a, b4[0], b4[2]);
                mma16816(accS[2 * i + 1], a, b4[1], b4[3]);
            }
        }

#pragma unroll
        for (int e = 0; e < 2; ++e) {
            float rmax = -1e30f;
#pragma unroll
            for (int nt = 0; nt < 16; nt++)
                rmax = fmaxf(rmax, fmaxf(accS[nt][2 * e], accS[nt][2 * e + 1]));
            rmax = fmaxf(rmax, __shfl_xor_sync(0xffffffffu, rmax, 1));
            rmax = fmaxf(rmax, __shfl_xor_sync(0xffffffffu, rmax, 2));
            const float mnew = fmaxf(mrow[e], rmax);
            const float corr = __expf(mrow[e] - mnew);
            mrow[e] = mnew;
            lrow_[e] *= corr;
#pragma unroll
            for (int nt = 0; nt < 8; nt++) {
                accO[nt][2 * e] *= corr;
                accO[nt][2 * e + 1] *= corr;
            }
            float sum = 0.f;
#pragma unroll
            for (int nt = 0; nt < 16; nt++) {
                const float p0 = __expf(accS[nt][2 * e] - mnew);
                const float p1 = __expf(accS[nt][2 * e + 1] - mnew);
                accS[nt][2 * e] = p0; accS[nt][2 * e + 1] = p1;
                sum += p0 + p1;
            }
            lrow_[e] += sum;
        }

#pragma unroll
        for (int j = 0; j < 8; ++j) {
            unsigned aP[4];
            aP[0] = packh2(accS[2 * j][0], accS[2 * j][1]);
            aP[1] = packh2(accS[2 * j][2], accS[2 * j][3]);
            aP[2] = packh2(accS[2 * j + 1][0], accS[2 * j + 1][1]);
            aP[3] = packh2(accS[2 * j + 1][2], accS[2 * j + 1][3]);
#pragma unroll
            for (int i = 0; i < 4; ++i) {
                unsigned b4[4];
                ldsm4t(b4, &Vs[j * 16 + (lane & 7) + ((lane >> 3) & 1) * 8]
                           [i * 16 + (lane >> 4) * 8]);
                mma16816(accO[2 * i], aP, b4[0], b4[1]);
                mma16816(accO[2 * i + 1], aP, b4[2], b4[3]);
            }
        }
    }

#pragma unroll
    for (int e = 0; e < 2; ++e) {
        float l = lrow_[e];
        l += __shfl_xor_sync(0xffffffffu, l, 1);
        l += __shfl_xor_sync(0xffffffffu, l, 2);
        const float inv = 1.0f / l;
        const int r = qt * 128 + wq + g + 8 * e;
#pragma unroll
        for (int nt = 0; nt < 8; nt++) {
            __half2 h = __floats2half2_rn(accO[nt][2 * e] * inv,
                                          accO[nt][2 * e + 1] * inv);
            *reinterpret_cast<__half2*>(O + (long)r * 4096 + vOff + nt * 8 + tg * 2) = h;
        }
    }
}

// ---------------------------------------------------------------------------
extern "C" void kernel_launch(void* const* d_in, const int* in_sizes, int n_in,
                              void* d_out, int out_size) {
    const float* src        = (const float*)d_in[0];
    const float* pos        = (const float*)d_in[1];
    const float* in_proj_w  = (const float*)d_in[2];
    const float* alpha_in   = (const float*)d_in[3];
    const float* out_proj_w = (const float*)d_in[4];
    const float* alpha_out  = (const float*)d_in[5];
    const float* w1         = (const float*)d_in[6];
    const float* b1         = (const float*)d_in[7];
    const float* alpha1     = (const float*)d_in[8];
    const float* w2         = (const float*)d_in[9];
    const float* b2         = (const float*)d_in[10];
    const float* alpha2     = (const float*)d_in[11];
    const float* ln1_g      = (const float*)d_in[12];
    const float* ln1_b      = (const float*)d_in[13];
    const float* ln2_g      = (const float*)d_in[14];
    const float* ln2_b      = (const float*)d_in[15];
    float* out = (float*)d_out;

    __half *win_q, *wout_q, *w1_q, *w2_q, *src2h, *qkh, *qk2, *vh;
    __half *ctxh, *src2bh, *hbufh;
    float *res;
    cudaGetSymbolAddress((void**)&win_q,  g_win_q);
    cudaGetSymbolAddress((void**)&wout_q, g_wout_q);
    cudaGetSymbolAddress((void**)&w1_q,   g_w1_q);
    cudaGetSymbolAddress((void**)&w2_q,   g_w2_q);
    cudaGetSymbolAddress((void**)&src2h,  g_src2h);
    cudaGetSymbolAddress((void**)&qkh,    g_qkh);
    cudaGetSymbolAddress((void**)&qk2,    g_qk2);
    cudaGetSymbolAddress((void**)&vh,     g_vh);
    cudaGetSymbolAddress((void**)&ctxh,   g_ctxh);
    cudaGetSymbolAddress((void**)&res,    g_res);
    cudaGetSymbolAddress((void**)&src2bh, g_src2bh);
    cudaGetSymbolAddress((void**)&hbufh,  g_hbufh);

    cudaFuncSetAttribute(hgemm,
                         cudaFuncAttributeMaxDynamicSharedMemorySize, HG_SMEM);
    cudaFuncSetAttribute(qkv_kernel,
                         cudaFuncAttributeMaxDynamicSharedMemorySize, HG_SMEM);
    cudaFuncSetAttribute(flash_kernel,
                         cudaFuncAttributeMaxDynamicSharedMemorySize, FL_SMEM);

    // 1) quantize all weights (single launch)
    quant4_kernel<<<12288, 256>>>(
        (const float4*)in_proj_w, (const float4*)out_proj_w,
        (const float4*)w1, (const float4*)w2,
        alpha_in, alpha_out, alpha1, alpha2,
        (uint2*)win_q, (uint2*)wout_q, (uint2*)w1_q, (uint2*)w2_q);

    // 2) LN1 -> src2h (fp16), qkh = LN + pos (fp16)
    ln_kernel<true><<<MROWS, 256>>>(src, ln1_g, ln1_b, pos, src2h, qkh);

    // 3) merged QKV projection (768 CTAs)
    qkv_kernel<<<dim3(3072 / 128, MROWS / 128), 128, HG_SMEM>>>(
        qkh, src2h, win_q, qk2, vh, alpha_in);

    // 4) fused attention -> ctxh
    flash_kernel<<<dim3(S_DIM / 128, NBH), 256, FL_SMEM>>>(qk2, vh, ctxh);

    // 5) res = src + ctx @ Wout^T * alpha_out   (fp32 out)
    hgemm<<<dim3(D_DIM / 128, MROWS / 128), 128, HG_SMEM>>>(
        ctxh, wout_q, res, nullptr, nullptr, src, alpha_out,
        D_DIM, D_DIM, D_DIM, D_DIM, 1.0f, 1.0f, 1 << 30, 0);

    // 6) LN2 -> src2bh (fp16)
    ln_kernel<false><<<MROWS, 256>>>(res, ln2_g, ln2_b, nullptr, src2bh, nullptr);

    // 7) FFN1: h = relu(src2b @ W1^T * alpha1 + b1)  -> fp16
    hgemm<<<dim3(DFF_DIM / 128, MROWS / 128), 128, HG_SMEM>>>(
        src2bh, w1_q, nullptr, hbufh, b1, nullptr, alpha1,
        D_DIM, D_DIM, D_DIM, DFF_DIM, 1.0f, 1.0f, 1 << 30, 1);

    // 8) FFN2: out = res + h @ W2^T * alpha2 + b2  (fp32 out, K=4096)
    hgemm<<<dim3(D_DIM / 128, MROWS / 128), 128, HG_SMEM>>>(
        hbufh, w2_q, out, nullptr, b2, res, alpha2,
        DFF_DIM, DFF_DIM, DFF_DIM, D_DIM, 1.0f, 1.0f, 1 << 30, 0);
}